// round 5
// baseline (speedup 1.0000x reference)
#include <cuda_runtime.h>
#include <cuda_bf16.h>
#include <math.h>
#include <cstdint>

// ---------------- problem constants ----------------
#define NQ   300
#define BSZ  8
#define DIM  256
#define NH   8
#define DH   32
#define DFF  1024
#define STOT 13294
#define NTOK (NQ*BSZ)          // 2400
#define TOKF (NTOK*DIM)        // 614400
#define MEMN ((long)STOT*BSZ*DIM)   // 27,226,112

// weight plane offsets (elements)
#define W_INPROJ 0L
#define W_OUTSA  196608L
#define W_VALUE  262144L
#define W_OFF    327680L
#define W_AW     458752L
#define W_OUTCA  524288L
#define W_LIN1   589824L
#define W_LIN2   851968L
#define W_TOTAL  1114112L

// ---------------- scratch (static device globals; no allocations) ----------------
__device__ float g_qh   [TOKF];
__device__ float g_kh   [TOKF];
__device__ float g_vh   [TOKF];
__device__ float g_saout[TOKF];
__device__ float g_tgt2 [TOKF];
__device__ float g_off  [NTOK*768];
__device__ float g_value[MEMN];
__device__ float g_caout[TOKF];
__device__ float g_tgt3 [TOKF];
__device__ float g_f2   [TOKF];

// bf16 hi/lo planes
__device__ __nv_bfloat16 g_memh[MEMN], g_meml[MEMN];
__device__ __nv_bfloat16 g_wh[W_TOTAL], g_wl[W_TOTAL];
__device__ __nv_bfloat16 g_qbh[TOKF], g_qbl[TOKF];     // tgt+mask (QK input)
__device__ __nv_bfloat16 g_tgh[TOKF], g_tgl[TOKF];     // tgt (V input)
__device__ __nv_bfloat16 g_sah[TOKF], g_sal[TOKF];     // attn out
__device__ __nv_bfloat16 g_q2h[TOKF], g_q2l[TOKF];     // query2
__device__ __nv_bfloat16 g_t3h[TOKF], g_t3l[TOKF];     // tgt3
__device__ __nv_bfloat16 g_f1h[NTOK*DFF], g_f1l[NTOK*DFF];
__device__ __nv_bfloat16 g_cah[TOKF], g_cal[TOKF];     // deform out

// ---------------- helpers ----------------
__device__ __forceinline__ uint32_t smem_u32(const void* p) {
    uint32_t a;
    asm("{ .reg .u64 t; cvta.to.shared.u64 t, %1; cvt.u32.u64 %0, t; }" : "=r"(a) : "l"(p));
    return a;
}
__device__ __forceinline__ unsigned pk2(__nv_bfloat16 a, __nv_bfloat16 b) {
    __nv_bfloat162 t = __halves2bfloat162(a, b);
    return *reinterpret_cast<unsigned*>(&t);
}
__device__ __forceinline__ void mma_bf16(float* d, const uint32_t* a, uint32_t b0, uint32_t b1) {
    asm volatile(
        "mma.sync.aligned.m16n8k16.row.col.f32.bf16.bf16.f32 "
        "{%0,%1,%2,%3}, {%4,%5,%6,%7}, {%8,%9}, {%0,%1,%2,%3};"
        : "+f"(d[0]), "+f"(d[1]), "+f"(d[2]), "+f"(d[3])
        : "r"(a[0]), "r"(a[1]), "r"(a[2]), "r"(a[3]), "r"(b0), "r"(b1));
}
__device__ __forceinline__ void ldmx4(uint32_t* r, uint32_t addr) {
    asm volatile("ldmatrix.sync.aligned.m8n8.x4.shared.b16 {%0,%1,%2,%3}, [%4];"
                 : "=r"(r[0]), "=r"(r[1]), "=r"(r[2]), "=r"(r[3]) : "r"(addr));
}
#define CP16(dst, src, sz) \
    asm volatile("cp.async.cg.shared.global [%0], [%1], 16, %2;" \
                 :: "r"(dst), "l"(src), "r"(sz) : "memory")
#define CP_COMMIT() asm volatile("cp.async.commit_group;" ::: "memory")
#define CP_WAIT1()  asm volatile("cp.async.wait_group 1;" ::: "memory")

__device__ __forceinline__ void split8(const float* v, unsigned* hi, unsigned* lo) {
    // v[0..3] -> hi[0..1], lo[0..1] packed bf16x2
    __nv_bfloat16 h[4], l[4];
#pragma unroll
    for (int i = 0; i < 4; i++) {
        h[i] = __float2bfloat16_rn(v[i]);
        l[i] = __float2bfloat16_rn(v[i] - __bfloat162float(h[i]));
    }
    hi[0] = pk2(h[0], h[1]); hi[1] = pk2(h[2], h[3]);
    lo[0] = pk2(l[0], l[1]); lo[1] = pk2(l[2], l[3]);
}

// ============ bf16 3-term pipelined GEMM: C = A(MxK)*W(NxK)^T + bias ============
// All operands pre-split bf16 hi/lo planes. CTA 128x128, 256 thr, 8 warps (32x64).
// cp.async 3-stage pipeline, K chunks of 32. Stage 32768 B:
//   Ahi 0, Alo 8192, Bhi 16384, Blo 24576. Rows 64B, swz c' = c ^ ((row>>1)&3).
// EPI: 0 plain fp32, 1 relu -> hi/lo planes (Chi/Clo), 2 head-permute fp32 (C/C2
//      split at n=256), 3 pad-mask fp32 (batched).
template<int EPI>
__global__ void __launch_bounds__(256, 2) mma_gemm(
    const __nv_bfloat16* __restrict__ Ahi, const __nv_bfloat16* __restrict__ Alo,
    int lda, long aOff,
    const __nv_bfloat16* __restrict__ Bhi, const __nv_bfloat16* __restrict__ Blo,
    int ldw, const float* __restrict__ bias,
    const __nv_bfloat16* W2hi, const __nv_bfloat16* W2lo,
    const float* bias2, int Nsplit,
    float* __restrict__ C, float* __restrict__ C2,
    __nv_bfloat16* __restrict__ Chi, __nv_bfloat16* __restrict__ Clo,
    int ldc, long cOff,
    int M, int K,
    const unsigned char* __restrict__ mask, long mOff)
{
    extern __shared__ __align__(128) unsigned char sm[];
    const uint32_t sb = smem_u32(sm);
    const int tid = threadIdx.x;
    const int bm = blockIdx.y * 128;
    const int bn = blockIdx.x * 128;
    Ahi += (long)blockIdx.z * aOff; Alo += (long)blockIdx.z * aOff;
    C   += (long)blockIdx.z * cOff;
    if (Nsplit && bn >= Nsplit) {
        Bhi = W2hi - (long)Nsplit * ldw;
        Blo = W2lo - (long)Nsplit * ldw;
        bias = bias2 - Nsplit;
    }

    const int warp = tid >> 5, lane = tid & 31;
    const int wm = warp & 3, wn = warp >> 2;

    // per-thread cp.async geometry: rows tid>>2 and +64, chunk tid&3
    const int r0 = tid >> 2, r1 = r0 + 64;
    const int ch = tid & 3;
    const uint32_t d0 = (uint32_t)(r0 * 64 + ((ch ^ ((r0 >> 1) & 3)) << 4));
    const uint32_t d1 = (uint32_t)(r1 * 64 + ((ch ^ ((r1 >> 1) & 3)) << 4));
    const int am0 = bm + r0 < M ? bm + r0 : M - 1;
    const int am1 = bm + r1 < M ? bm + r1 : M - 1;
    const uint32_t sz0 = (bm + r0 < M) ? 16u : 0u;
    const uint32_t sz1 = (bm + r1 < M) ? 16u : 0u;
    const long aro0 = (long)am0 * lda + ch * 8;
    const long aro1 = (long)am1 * lda + ch * 8;
    const long bro0 = (long)(bn + r0) * ldw + ch * 8;
    const long bro1 = (long)(bn + r1) * ldw + ch * 8;

    const int nk = K >> 5;

#define ISSUE(kc, st) do { \
    if ((kc) < nk) { \
        const int kb = (kc) * 32; \
        const uint32_t so = sb + (uint32_t)((st) * 32768); \
        CP16(so + d0,          Ahi + aro0 + kb, sz0); \
        CP16(so + d1,          Ahi + aro1 + kb, sz1); \
        CP16(so + 8192  + d0,  Alo + aro0 + kb, sz0); \
        CP16(so + 8192  + d1,  Alo + aro1 + kb, sz1); \
        CP16(so + 16384 + d0,  Bhi + bro0 + kb, 16u); \
        CP16(so + 16384 + d1,  Bhi + bro1 + kb, 16u); \
        CP16(so + 24576 + d0,  Blo + bro0 + kb, 16u); \
        CP16(so + 24576 + d1,  Blo + bro1 + kb, 16u); \
    } \
    CP_COMMIT(); \
} while (0)

    float acc[2][8][4];
#pragma unroll
    for (int mt = 0; mt < 2; mt++)
#pragma unroll
        for (int nt = 0; nt < 8; nt++)
#pragma unroll
            for (int r = 0; r < 4; r++) acc[mt][nt][r] = 0.f;

    ISSUE(0, 0);
    ISSUE(1, 1);

    for (int kc = 0; kc < nk; kc++) {
        CP_WAIT1();
        __syncthreads();
        ISSUE(kc + 2, (kc + 2) % 3);

        const uint32_t so = sb + (uint32_t)((kc % 3) * 32768);
#pragma unroll
        for (int ks = 0; ks < 2; ks++) {
            uint32_t ahi[2][4], alo[2][4];
#pragma unroll
            for (int mt = 0; mt < 2; mt++) {
                int row = wm * 32 + mt * 16 + (lane & 7) + ((lane >> 3) & 1) * 8;
                int c = 2 * ks + (lane >> 4);
                uint32_t off = (uint32_t)(row * 64 + ((c ^ ((row >> 1) & 3)) << 4));
                ldmx4(ahi[mt], so + off);
                ldmx4(alo[mt], so + 8192 + off);
            }
            uint32_t bhi[8][2], blo[8][2];
#pragma unroll
            for (int np = 0; np < 4; np++) {
                int row = wn * 64 + np * 16 + (lane & 7) + (lane >> 4) * 8;
                int c = 2 * ks + ((lane >> 3) & 1);
                uint32_t off = (uint32_t)(row * 64 + ((c ^ ((row >> 1) & 3)) << 4));
                uint32_t t[4];
                ldmx4(t, so + 16384 + off);
                bhi[2*np][0] = t[0]; bhi[2*np][1] = t[1];
                bhi[2*np+1][0] = t[2]; bhi[2*np+1][1] = t[3];
                ldmx4(t, so + 24576 + off);
                blo[2*np][0] = t[0]; blo[2*np][1] = t[1];
                blo[2*np+1][0] = t[2]; blo[2*np+1][1] = t[3];
            }
#pragma unroll
            for (int mt = 0; mt < 2; mt++)
#pragma unroll
                for (int nt = 0; nt < 8; nt++) {
                    mma_bf16(acc[mt][nt], ahi[mt], bhi[nt][0], bhi[nt][1]);
                    mma_bf16(acc[mt][nt], ahi[mt], blo[nt][0], blo[nt][1]);
                    mma_bf16(acc[mt][nt], alo[mt], bhi[nt][0], bhi[nt][1]);
                }
        }
    }
#undef ISSUE

    // ---------------- epilogue ----------------
#pragma unroll
    for (int mt = 0; mt < 2; mt++) {
        int rb = bm + wm * 32 + mt * 16 + (lane >> 2);
#pragma unroll
        for (int nt = 0; nt < 8; nt++) {
            int n0 = bn + wn * 64 + nt * 8 + (lane & 3) * 2;
            float b0 = bias[n0], b1 = bias[n0 + 1];
#pragma unroll
            for (int half = 0; half < 2; half++) {
                int r = rb + half * 8;
                if (r >= M) continue;
                float v0 = acc[mt][nt][half * 2 + 0] + b0;
                float v1 = acc[mt][nt][half * 2 + 1] + b1;
                if (EPI == 1) {
                    v0 = fmaxf(v0, 0.f); v1 = fmaxf(v1, 0.f);
                    __nv_bfloat16 h0 = __float2bfloat16_rn(v0);
                    __nv_bfloat16 h1 = __float2bfloat16_rn(v1);
                    long p = (long)r * ldc + n0;
                    *(__nv_bfloat162*)(Chi + p) = __halves2bfloat162(h0, h1);
                    *(__nv_bfloat162*)(Clo + p) = __halves2bfloat162(
                        __float2bfloat16_rn(v0 - __bfloat162float(h0)),
                        __float2bfloat16_rn(v1 - __bfloat162float(h1)));
                } else if (EPI == 2) {
                    float* base = C; int nn = n0;
                    if (nn >= 256) { base = C2; nn -= 256; }
                    int q = r >> 3, bb = r & 7, hh = nn >> 5, d = nn & 31;
                    float* p = base + (((long)(bb * NH + hh)) * NQ + q) * DH + d;
                    p[0] = v0; p[1] = v1;
                } else {
                    if (EPI == 3 && mask[(long)blockIdx.z * mOff + r]) { v0 = 0.f; v1 = 0.f; }
                    float* p = C + (long)r * ldc + n0;
                    p[0] = v0; p[1] = v1;
                }
            }
        }
    }
}

static inline void launch_mma(int epi,
    const __nv_bfloat16* Ahi, const __nv_bfloat16* Alo, int lda, long aOff,
    const __nv_bfloat16* Bhi, const __nv_bfloat16* Blo, int ldw, const float* bias,
    const __nv_bfloat16* W2hi, const __nv_bfloat16* W2lo, const float* bias2, int Nsplit,
    float* C, float* C2, __nv_bfloat16* Chi, __nv_bfloat16* Clo, int ldc, long cOff,
    int M, int N, int K, int nz,
    const unsigned char* mask, long mOff)
{
    dim3 grid(N / 128, (M + 127) / 128, nz);
    const int SMEM = 3 * 32768;
#define LM(E) do { \
    cudaFuncSetAttribute(mma_gemm<E>, cudaFuncAttributeMaxDynamicSharedMemorySize, SMEM); \
    mma_gemm<E><<<grid,256,SMEM>>>(Ahi,Alo,lda,aOff,Bhi,Blo,ldw,bias,W2hi,W2lo,bias2,Nsplit, \
                                   C,C2,Chi,Clo,ldc,cOff,M,K,mask,mOff); } while (0)
    switch (epi) {
        case 0: LM(0); break;
        case 1: LM(1); break;
        case 2: LM(2); break;
        case 3: LM(3); break;
    }
#undef LM
}

// ---------------- converts ----------------
__global__ void cvt_kernel(const float* __restrict__ src,
                           __nv_bfloat16* __restrict__ hi, __nv_bfloat16* __restrict__ lo,
                           long n4)
{
    long i = (long)blockIdx.x * blockDim.x + threadIdx.x;
    if (i >= n4) return;
    float4 v = ((const float4*)src)[i];
    unsigned h[2], l[2];
    split8(&v.x, h, l);
    ((uint2*)hi)[i] = make_uint2(h[0], h[1]);
    ((uint2*)lo)[i] = make_uint2(l[0], l[1]);
}

struct WDesc { const float* src[8]; long off[8]; int n4[8]; };
__global__ void cvt_w_kernel(WDesc d, __nv_bfloat16* __restrict__ hi, __nv_bfloat16* __restrict__ lo)
{
    int w = blockIdx.y;
    int i = blockIdx.x * blockDim.x + threadIdx.x;
    if (i >= d.n4[w]) return;
    float4 v = ((const float4*)d.src[w])[i];
    unsigned h[2], l[2];
    split8(&v.x, h, l);
    ((uint2*)(hi + d.off[w]))[i] = make_uint2(h[0], h[1]);
    ((uint2*)(lo + d.off[w]))[i] = make_uint2(l[0], l[1]);
}

// q = a + b -> hi/lo planes (same layout)
__global__ void add_cvt_kernel(const float* __restrict__ a, const float* __restrict__ b,
                               __nv_bfloat16* __restrict__ hi, __nv_bfloat16* __restrict__ lo)
{
    int i = blockIdx.x * 256 + threadIdx.x;
    if (i >= TOKF/4) return;
    float4 x = ((const float4*)a)[i], y = ((const float4*)b)[i];
    float v[4] = {x.x+y.x, x.y+y.y, x.z+y.z, x.w+y.w};
    unsigned h[2], l[2];
    split8(v, h, l);
    ((uint2*)hi)[i] = make_uint2(h[0], h[1]);
    ((uint2*)lo)[i] = make_uint2(l[0], l[1]);
}

// query2 planes in (b,q,d) layout from tgt2 (q,b,d) + mask
__global__ void permadd_cvt_kernel(const float* __restrict__ t2, const float* __restrict__ msk,
                                   __nv_bfloat16* __restrict__ hi, __nv_bfloat16* __restrict__ lo)
{
    int i = blockIdx.x * 256 + threadIdx.x;
    if (i >= TOKF/4) return;
    int d4 = i & 63;
    int t = i >> 6;
    int q = t >> 3, b = t & 7;
    float4 x = ((const float4*)t2)[i], y = ((const float4*)msk)[i];
    float v[4] = {x.x+y.x, x.y+y.y, x.z+y.z, x.w+y.w};
    unsigned h[2], l[2];
    split8(v, h, l);
    long o = ((long)(b*NQ + q) << 6) + d4;
    ((uint2*)hi)[o] = make_uint2(h[0], h[1]);
    ((uint2*)lo)[o] = make_uint2(l[0], l[1]);
}

// ---------------- residual + layernorm (optional hi/lo plane out) ----------------
__global__ void __launch_bounds__(256) ln_kernel(
    const float* __restrict__ A, const float* __restrict__ B, int bBQ,
    const float* __restrict__ g, const float* __restrict__ be,
    float* __restrict__ out,
    __nv_bfloat16* __restrict__ ohi, __nv_bfloat16* __restrict__ olo)
{
    int t = blockIdx.x * 8 + (threadIdx.x >> 5);
    int lane = threadIdx.x & 31;
    if (t >= NTOK) return;
    const float* ap = A + (long)t * DIM + lane*8;
    long bo;
    if (bBQ) { int q = t >> 3, b = t & 7; bo = (long)(b*NQ + q) * DIM; }
    else     { bo = (long)t * DIM; }
    const float* bp = B + bo + lane*8;

    float4 x0 = *(const float4*)ap,      x1 = *(const float4*)(ap + 4);
    float4 y0 = *(const float4*)bp,      y1 = *(const float4*)(bp + 4);
    float v[8] = {x0.x+y0.x, x0.y+y0.y, x0.z+y0.z, x0.w+y0.w,
                  x1.x+y1.x, x1.y+y1.y, x1.z+y1.z, x1.w+y1.w};
    float s = 0.f;
#pragma unroll
    for (int i = 0; i < 8; i++) s += v[i];
#pragma unroll
    for (int o = 16; o; o >>= 1) s += __shfl_xor_sync(0xffffffffu, s, o);
    float mu = s * (1.f/256.f);
    float s2 = 0.f;
#pragma unroll
    for (int i = 0; i < 8; i++) { float d = v[i] - mu; s2 += d*d; }
#pragma unroll
    for (int o = 16; o; o >>= 1) s2 += __shfl_xor_sync(0xffffffffu, s2, o);
    float inv = rsqrtf(s2 * (1.f/256.f) + 1e-5f);
    int c0 = lane*8;
    float* op = out + (long)t * DIM + c0;
    float r[8];
#pragma unroll
    for (int i = 0; i < 8; i++) {
        r[i] = (v[i] - mu) * inv * g[c0+i] + be[c0+i];
        op[i] = r[i];
    }
    if (ohi) {
        unsigned h[2], l[2];
        split8(r, h, l);
        unsigned h2[2], l2[2];
        split8(r + 4, h2, l2);
        long o4 = ((long)t * DIM + c0) >> 2;
        ((uint2*)ohi)[o4]   = make_uint2(h[0], h[1]);
        ((uint2*)ohi)[o4+1] = make_uint2(h2[0], h2[1]);
        ((uint2*)olo)[o4]   = make_uint2(l[0], l[1]);
        ((uint2*)olo)[o4+1] = make_uint2(l2[0], l2[1]);
    }
}

// ---------------- fused self-attention (writes hi/lo planes) ----------------
__global__ void __launch_bounds__(256) attn_kernel(
    const float* __restrict__ qh, const float* __restrict__ kh,
    const float* __restrict__ vh,
    __nv_bfloat16* __restrict__ sah, __nv_bfloat16* __restrict__ sal)
{
    extern __shared__ float smf[];
    const int bh   = blockIdx.x >> 1;
    const int half = blockIdx.x & 1;
    const int b = bh >> 3, h = bh & 7;
    float* Ks = smf;
    float* Vs = Ks + 300*36;
    float* Qs = Vs + 300*36;
    float* Ps = Qs + 150*32;

    const float scale = 0.17677669529663687f;
    const float* Kg = kh + (long)bh * NQ * DH;
    const float* Vg = vh + (long)bh * NQ * DH;
    const float* Qg = qh + (long)bh * NQ * DH + (long)half * 150 * DH;
    const int tid = threadIdx.x;

    for (int i = tid; i < 2400; i += 256) {
        int r = i >> 3, c4 = (i & 7) << 2;
        float4 kv = *(const float4*)(Kg + r*32 + c4);
        float4 vv = *(const float4*)(Vg + r*32 + c4);
        *(float4*)(Ks + r*36 + c4) = kv;
        *(float4*)(Vs + r*36 + c4) = vv;
    }
    for (int i = tid; i < 1200; i += 256) {
        int r = i >> 3, c4 = (i & 7) << 2;
        float4 qv = *(const float4*)(Qg + r*32 + c4);
        qv.x *= scale; qv.y *= scale; qv.z *= scale; qv.w *= scale;
        *(float4*)(Qs + r*32 + c4) = qv;
    }
    __syncthreads();

    const int warp = tid >> 5, lane = tid & 31;
    float* Pw = Ps + warp * 320;

    for (int q = warp; q < 150; q += 8) {
        float4 qr[8];
#pragma unroll
        for (int d4 = 0; d4 < 8; d4++) qr[d4] = *(const float4*)(Qs + q*32 + d4*4);

        float sc[10];
#pragma unroll
        for (int j = 0; j < 10; j++) {
            int k = j*32 + lane;
            float s = -1e30f;
            if (k < 300) {
                s = 0.f;
#pragma unroll
                for (int d4 = 0; d4 < 8; d4++) {
                    float4 kv = *(const float4*)(Ks + k*36 + d4*4);
                    s = fmaf(qr[d4].x, kv.x, s);
                    s = fmaf(qr[d4].y, kv.y, s);
                    s = fmaf(qr[d4].z, kv.z, s);
                    s = fmaf(qr[d4].w, kv.w, s);
                }
            }
            sc[j] = s;
        }
        float m = sc[0];
#pragma unroll
        for (int j = 1; j < 10; j++) m = fmaxf(m, sc[j]);
#pragma unroll
        for (int o = 16; o; o >>= 1) m = fmaxf(m, __shfl_xor_sync(0xffffffffu, m, o));
        float sum = 0.f;
#pragma unroll
        for (int j = 0; j < 10; j++) { sc[j] = expf(sc[j] - m); sum += sc[j]; }
#pragma unroll
        for (int o = 16; o; o >>= 1) sum += __shfl_xor_sync(0xffffffffu, sum, o);
        float inv = 1.f / sum;
#pragma unroll
        for (int j = 0; j < 10; j++) Pw[j*32 + lane] = sc[j] * inv;
        __syncwarp();

        float acc = 0.f;
#pragma unroll 4
        for (int k = 0; k < 300; k++)
            acc = fmaf(Pw[k], Vs[k*36 + lane], acc);

        int qg = half*150 + q;
        long o = ((long)(qg*BSZ + b)) * DIM + h*DH + lane;
        __nv_bfloat16 hi = __float2bfloat16_rn(acc);
        sah[o] = hi;
        sal[o] = __float2bfloat16_rn(acc - __bfloat162float(hi));
        __syncwarp();
    }
}

// ---------------- multi-scale deformable sampling (writes hi/lo planes) ----------------
__global__ void __launch_bounds__(256) deform_kernel(
    const float* __restrict__ offaw,
    const float* __restrict__ bbox, const float* __restrict__ value,
    const int* __restrict__ spatial, const int* __restrict__ lstart,
    __nv_bfloat16* __restrict__ cah, __nv_bfloat16* __restrict__ cal)
{
    __shared__ float s_w[8][32][4];
    __shared__ int   s_i[8][32][4];
    int bq = blockIdx.x;
    int b = bq / NQ, q = bq - b*NQ;
    int warp = threadIdx.x >> 5, lane = threadIdx.x & 31;

    const float* tok = offaw + (long)bq * 768;
    float a = tok[512 + warp*32 + lane];
    float m = a;
#pragma unroll
    for (int o = 16; o; o >>= 1) m = fmaxf(m, __shfl_xor_sync(0xffffffffu, m, o));
    float e = expf(a - m);
    float s = e;
#pragma unroll
    for (int o = 16; o; o >>= 1) s += __shfl_xor_sync(0xffffffffu, s, o);
    float p = e / s;

    float ox = tok[warp*64 + lane*2];
    float oy = tok[warp*64 + lane*2 + 1];
    const float* rb = bbox + ((long)q*BSZ + b)*4;
    float r0 = rb[0], r1 = rb[1], r2 = rb[2], r3 = rb[3];

    int lvl = lane >> 3;
    int H = spatial[lvl*2], W = spatial[lvl*2 + 1], ls = lstart[lvl];
    float Wf = (float)W, Hf = (float)H;
    float x = (r0 + ox*0.0625f*r2) * Wf - 0.5f;
    float y = (r1 + oy*0.0625f*r3) * Hf - 0.5f;
    float x0 = floorf(x), y0 = floorf(y);
    float fx = x - x0, fy = y - y0;

#pragma unroll
    for (int c = 0; c < 4; c++) {
        float xi = x0 + (float)(c & 1);
        float yi = y0 + (float)(c >> 1);
        float wgt = ((c & 1) ? fx : 1.f - fx) * ((c >> 1) ? fy : 1.f - fy);
        bool valid = (xi >= 0.f) && (xi < Wf) && (yi >= 0.f) && (yi < Hf);
        int xc = (int)fminf(fmaxf(xi, 0.f), Wf - 1.f);
        int yc = (int)fminf(fmaxf(yi, 0.f), Hf - 1.f);
        s_i[warp][lane][c] = ls + yc*W + xc;
        s_w[warp][lane][c] = valid ? wgt * p : 0.f;
    }
    __syncwarp();

    const float* vb = value + (long)b * STOT * DIM + warp*DH + lane;
    float acc = 0.f;
    for (int lp = 0; lp < 32; lp++) {
#pragma unroll
        for (int c = 0; c < 4; c++) {
            float wgt = s_w[warp][lp][c];
            if (wgt != 0.f)
                acc = fmaf(wgt, vb[(long)s_i[warp][lp][c] << 8], acc);
        }
    }
    long o = (long)bq*DIM + warp*DH + lane;
    __nv_bfloat16 hi = __float2bfloat16_rn(acc);
    cah[o] = hi;
    cal[o] = __float2bfloat16_rn(acc - __bfloat162float(hi));
}

// ---------------- host orchestration ----------------
extern "C" void kernel_launch(void* const* d_in, const int* in_sizes, int n_in,
                              void* d_out, int out_size)
{
    const float* tgt        = (const float*)d_in[0];
    const float* qmask      = (const float*)d_in[1];
    const float* bbox       = (const float*)d_in[2];
    const float* memory     = (const float*)d_in[4];
    const float* in_proj_w  = (const float*)d_in[5];
    const float* in_proj_b  = (const float*)d_in[6];
    const float* out_sa_w   = (const float*)d_in[7];
    const float* out_sa_b   = (const float*)d_in[8];
    const float* norm2_g    = (const float*)d_in[9];
    const float* norm2_b    = (const float*)d_in[10];
    const float* value_w    = (const float*)d_in[11];
    const float* value_b    = (const float*)d_in[12];
    const float* off_w      = (const float*)d_in[13];
    const float* off_b      = (const float*)d_in[14];
    const float* aw_w       = (const float*)d_in[15];
    const float* aw_b       = (const float*)d_in[16];
    const float* out_ca_w   = (const float*)d_in[17];
    const float* out_ca_b   = (const float*)d_in[18];
    const float* norm1_g    = (const float*)d_in[19];
    const float* norm1_b    = (const float*)d_in[20];
    const float* lin1_w     = (const float*)d_in[21];
    const float* lin1_b     = (const float*)d_in[22];
    const float* lin2_w     = (const float*)d_in[23];
    const float* lin2_b     = (const float*)d_in[24];
    const float* norm3_g    = (const float*)d_in[25];
    const float* norm3_b    = (const float*)d_in[26];
    const unsigned char* pmask = (const unsigned char*)d_in[27];
    const int* spatial      = (const int*)d_in[28];
    const int* lstart       = (const int*)d_in[29];
    float* out = (float*)d_out;

    float *qhp,*khp,*vhp,*saout,*tgt2,*offb,*val,*caout,*tgt3,*f2;
    __nv_bfloat16 *memh,*meml,*wh,*wl,*qbh,*qbl,*tgh,*tgl,*sah,*sal,*q2h,*q2l,*t3h,*t3l,*f1h,*f1l,*cah,*cal;
    cudaGetSymbolAddress((void**)&qhp,   g_qh);
    cudaGetSymbolAddress((void**)&khp,   g_kh);
    cudaGetSymbolAddress((void**)&vhp,   g_vh);
    cudaGetSymbolAddress((void**)&saout, g_saout);
    cudaGetSymbolAddress((void**)&tgt2,  g_tgt2);
    cudaGetSymbolAddress((void**)&offb,  g_off);
    cudaGetSymbolAddress((void**)&val,   g_value);
    cudaGetSymbolAddress((void**)&caout, g_caout);
    cudaGetSymbolAddress((void**)&tgt3,  g_tgt3);
    cudaGetSymbolAddress((void**)&f2,    g_f2);
    cudaGetSymbolAddress((void**)&memh,  g_memh);
    cudaGetSymbolAddress((void**)&meml,  g_meml);
    cudaGetSymbolAddress((void**)&wh,    g_wh);
    cudaGetSymbolAddress((void**)&wl,    g_wl);
    cudaGetSymbolAddress((void**)&qbh,   g_qbh);
    cudaGetSymbolAddress((void**)&qbl,   g_qbl);
    cudaGetSymbolAddress((void**)&tgh,   g_tgh);
    cudaGetSymbolAddress((void**)&tgl,   g_tgl);
    cudaGetSymbolAddress((void**)&sah,   g_sah);
    cudaGetSymbolAddress((void**)&sal,   g_sal);
    cudaGetSymbolAddress((void**)&q2h,   g_q2h);
    cudaGetSymbolAddress((void**)&q2l,   g_q2l);
    cudaGetSymbolAddress((void**)&t3h,   g_t3h);
    cudaGetSymbolAddress((void**)&t3l,   g_t3l);
    cudaGetSymbolAddress((void**)&f1h,   g_f1h);
    cudaGetSymbolAddress((void**)&f1l,   g_f1l);
    cudaGetSymbolAddress((void**)&cah,   g_cah);
    cudaGetSymbolAddress((void**)&cal,   g_cal);

    // 0) converts: memory, tgt, weights, qbuf
    cvt_kernel<<<(unsigned)(MEMN/4/256), 256>>>(memory, memh, meml, MEMN/4);
    cvt_kernel<<<TOKF/4/256, 256>>>(tgt, tgh, tgl, TOKF/4);
    {
        WDesc d;
        d.src[0]=in_proj_w; d.off[0]=W_INPROJ; d.n4[0]=196608/4;
        d.src[1]=out_sa_w;  d.off[1]=W_OUTSA;  d.n4[1]=65536/4;
        d.src[2]=value_w;   d.off[2]=W_VALUE;  d.n4[2]=65536/4;
        d.src[3]=off_w;     d.off[3]=W_OFF;    d.n4[3]=131072/4;
        d.src[4]=aw_w;      d.off[4]=W_AW;     d.n4[4]=65536/4;
        d.src[5]=out_ca_w;  d.off[5]=W_OUTCA;  d.n4[5]=65536/4;
        d.src[6]=lin1_w;    d.off[6]=W_LIN1;   d.n4[6]=262144/4;
        d.src[7]=lin2_w;    d.off[7]=W_LIN2;   d.n4[7]=262144/4;
        dim3 g((262144/4 + 255)/256, 8);
        cvt_w_kernel<<<g, 256>>>(d, wh, wl);
    }
    add_cvt_kernel<<<TOKF/4/256, 256>>>(tgt, qmask, qbh, qbl);

    // 1) value projection (batched over BS), pad-mask epilogue
    launch_mma(3, memh, meml, BSZ*DIM, 256, wh+W_VALUE, wl+W_VALUE, DIM, value_b,
               nullptr, nullptr, nullptr, 0,
               val, nullptr, nullptr, nullptr, DIM, (long)STOT*DIM,
               STOT, DIM, DIM, BSZ, pmask, STOT);

    // 2) Q+K merged (N=512), then V
    launch_mma(2, qbh, qbl, DIM, 0, wh+W_INPROJ, wl+W_INPROJ, DIM, in_proj_b,
               nullptr, nullptr, nullptr, 0,
               qhp, khp, nullptr, nullptr, 0, 0, NTOK, 512, DIM, 1, nullptr, 0);
    launch_mma(2, tgh, tgl, DIM, 0, wh+W_INPROJ+512*256, wl+W_INPROJ+512*256, DIM, in_proj_b+512,
               nullptr, nullptr, nullptr, 0,
               vhp, vhp, nullptr, nullptr, 0, 0, NTOK, 256, DIM, 1, nullptr, 0);

    // 3) fused self-attention -> sa planes
    {
        int smem = (300*36*2 + 150*32 + 8*320) * 4;
        cudaFuncSetAttribute(attn_kernel, cudaFuncAttributeMaxDynamicSharedMemorySize, smem);
        attn_kernel<<<128, 256, smem>>>(qhp, khp, vhp, sah, sal);
    }

    // 4) self-attn out-proj + residual LN (norm2)
    launch_mma(0, sah, sal, DIM, 0, wh+W_OUTSA, wl+W_OUTSA, DIM, out_sa_b,
               nullptr, nullptr, nullptr, 0,
               saout, nullptr, nullptr, nullptr, DIM, 0, NTOK, 256, DIM, 1, nullptr, 0);
    ln_kernel<<<NTOK/8, 256>>>(tgt, saout, 0, norm2_g, norm2_b, tgt2, nullptr, nullptr);

    // 5) query2 planes in (b,q,d)
    permadd_cvt_kernel<<<(TOKF/4 + 255)/256, 256>>>(tgt2, qmask, q2h, q2l);

    // 6) offsets + aw logits merged (N=768, split at 512)
    launch_mma(0, q2h, q2l, DIM, 0, wh+W_OFF, wl+W_OFF, DIM, off_b,
               wh+W_AW, wl+W_AW, aw_b, 512,
               offb, nullptr, nullptr, nullptr, 768, 0, NTOK, 768, DIM, 1, nullptr, 0);

    // 7) deformable sampling -> ca planes
    deform_kernel<<<NTOK, 256>>>(offb, bbox, val, spatial, lstart, cah, cal);

    // 8) cross-attn out-proj + residual LN (norm1) -> tgt3 (+ planes)
    launch_mma(0, cah, cal, DIM, 0, wh+W_OUTCA, wl+W_OUTCA, DIM, out_ca_b,
               nullptr, nullptr, nullptr, 0,
               caout, nullptr, nullptr, nullptr, DIM, 0, NTOK, 256, DIM, 1, nullptr, 0);
    ln_kernel<<<NTOK/8, 256>>>(tgt2, caout, 1, norm1_g, norm1_b, tgt3, t3h, t3l);

    // 9) FFN (lin1 -> relu hi/lo planes; lin2 -> fp32) + final LN -> d_out
    launch_mma(1, t3h, t3l, DIM, 0, wh+W_LIN1, wl+W_LIN1, DIM, lin1_b,
               nullptr, nullptr, nullptr, 0,
               nullptr, nullptr, f1h, f1l, DFF, 0, NTOK, DFF, DIM, 1, nullptr, 0);
    launch_mma(0, f1h, f1l, DFF, 0, wh+W_LIN2, wl+W_LIN2, DFF, lin2_b,
               nullptr, nullptr, nullptr, 0,
               f2, nullptr, nullptr, nullptr, DIM, 0, NTOK, 256, DFF, 1, nullptr, 0);
    ln_kernel<<<NTOK/8, 256>>>(tgt3, f2, 0, norm3_g, norm3_b, out, nullptr, nullptr);
}

// round 6
// speedup vs baseline: 1.0213x; 1.0213x over previous
#include <cuda_runtime.h>
#include <cuda_bf16.h>
#include <math.h>
#include <cstdint>

// ---------------- problem constants ----------------
#define NQ   300
#define BSZ  8
#define DIM  256
#define NH   8
#define DH   32
#define DFF  1024
#define STOT 13294
#define NTOK (NQ*BSZ)          // 2400
#define TOKF (NTOK*DIM)        // 614400
#define MEMN ((long)STOT*BSZ*DIM)   // 27,226,112

// weight plane offsets (elements)
#define W_INPROJ 0L
#define W_OUTSA  196608L
#define W_VALUE  262144L
#define W_OFF    327680L
#define W_AW     458752L
#define W_OUTCA  524288L
#define W_LIN1   589824L
#define W_LIN2   851968L
#define W_TOTAL  1114112L

// ---------------- scratch (static device globals; no allocations) ----------------
__device__ float g_qh   [TOKF];
__device__ float g_kh   [TOKF];
__device__ float g_vh   [TOKF];
__device__ float g_saout[TOKF];
__device__ float g_tgt2 [TOKF];
__device__ float g_off  [NTOK*768];
__device__ float g_value[MEMN];
__device__ float g_caout[TOKF];
__device__ float g_tgt3 [TOKF];
__device__ float g_f2   [TOKF];

// bf16 hi/lo planes
__device__ __nv_bfloat16 g_memh[MEMN], g_meml[MEMN];
__device__ __nv_bfloat16 g_wh[W_TOTAL], g_wl[W_TOTAL];
__device__ __nv_bfloat16 g_qbh[TOKF], g_qbl[TOKF];     // tgt+mask (QK input)
__device__ __nv_bfloat16 g_tgh[TOKF], g_tgl[TOKF];     // tgt (V input)
__device__ __nv_bfloat16 g_sah[TOKF], g_sal[TOKF];     // attn out
__device__ __nv_bfloat16 g_q2h[TOKF], g_q2l[TOKF];     // query2
__device__ __nv_bfloat16 g_t3h[TOKF], g_t3l[TOKF];     // tgt3
__device__ __nv_bfloat16 g_f1h[NTOK*DFF], g_f1l[NTOK*DFF];
__device__ __nv_bfloat16 g_cah[TOKF], g_cal[TOKF];     // deform out

// ---------------- helpers ----------------
__device__ __forceinline__ uint32_t smem_u32(const void* p) {
    uint32_t a;
    asm("{ .reg .u64 t; cvta.to.shared.u64 t, %1; cvt.u32.u64 %0, t; }" : "=r"(a) : "l"(p));
    return a;
}
__device__ __forceinline__ unsigned pk2(__nv_bfloat16 a, __nv_bfloat16 b) {
    __nv_bfloat162 t = __halves2bfloat162(a, b);
    return *reinterpret_cast<unsigned*>(&t);
}
__device__ __forceinline__ void mma_bf16(float* d, const uint32_t* a, uint32_t b0, uint32_t b1) {
    asm volatile(
        "mma.sync.aligned.m16n8k16.row.col.f32.bf16.bf16.f32 "
        "{%0,%1,%2,%3}, {%4,%5,%6,%7}, {%8,%9}, {%0,%1,%2,%3};"
        : "+f"(d[0]), "+f"(d[1]), "+f"(d[2]), "+f"(d[3])
        : "r"(a[0]), "r"(a[1]), "r"(a[2]), "r"(a[3]), "r"(b0), "r"(b1));
}
__device__ __forceinline__ void ldmx4(uint32_t* r, uint32_t addr) {
    asm volatile("ldmatrix.sync.aligned.m8n8.x4.shared.b16 {%0,%1,%2,%3}, [%4];"
                 : "=r"(r[0]), "=r"(r[1]), "=r"(r[2]), "=r"(r[3]) : "r"(addr));
}
#define CP16(dst, src, sz) \
    asm volatile("cp.async.cg.shared.global [%0], [%1], 16, %2;" \
                 :: "r"(dst), "l"(src), "r"(sz) : "memory")
#define CP_COMMIT() asm volatile("cp.async.commit_group;" ::: "memory")
#define CP_WAIT1()  asm volatile("cp.async.wait_group 1;" ::: "memory")

__device__ __forceinline__ void split8(const float* v, unsigned* hi, unsigned* lo) {
    __nv_bfloat16 h[4], l[4];
#pragma unroll
    for (int i = 0; i < 4; i++) {
        h[i] = __float2bfloat16_rn(v[i]);
        l[i] = __float2bfloat16_rn(v[i] - __bfloat162float(h[i]));
    }
    hi[0] = pk2(h[0], h[1]); hi[1] = pk2(h[2], h[3]);
    lo[0] = pk2(l[0], l[1]); lo[1] = pk2(l[2], l[3]);
}

// ============ bf16 3-term pipelined GEMM: C = A(MxK)*W(NxK)^T + bias ============
// Operands pre-split bf16 hi/lo planes. CTA 128x128, 256 thr, 8 warps (32x64).
// cp.async 3-stage pipeline, K chunks of 32.
template<int EPI>
__global__ void __launch_bounds__(256, 2) mma_gemm(
    const __nv_bfloat16* __restrict__ Ahi, const __nv_bfloat16* __restrict__ Alo,
    int lda, long aOff,
    const __nv_bfloat16* __restrict__ Bhi, const __nv_bfloat16* __restrict__ Blo,
    int ldw, const float* __restrict__ bias,
    const __nv_bfloat16* W2hi, const __nv_bfloat16* W2lo,
    const float* bias2, int Nsplit,
    float* __restrict__ C, float* __restrict__ C2,
    __nv_bfloat16* __restrict__ Chi, __nv_bfloat16* __restrict__ Clo,
    int ldc, long cOff,
    int M, int K,
    const unsigned char* __restrict__ mask, long mOff)
{
    extern __shared__ __align__(128) unsigned char sm[];
    const uint32_t sb = smem_u32(sm);
    const int tid = threadIdx.x;
    const int bm = blockIdx.y * 128;
    const int bn = blockIdx.x * 128;
    Ahi += (long)blockIdx.z * aOff; Alo += (long)blockIdx.z * aOff;
    C   += (long)blockIdx.z * cOff;
    if (Nsplit && bn >= Nsplit) {
        Bhi = W2hi - (long)Nsplit * ldw;
        Blo = W2lo - (long)Nsplit * ldw;
        bias = bias2 - Nsplit;
    }

    const int warp = tid >> 5, lane = tid & 31;
    const int wm = warp & 3, wn = warp >> 2;

    const int r0 = tid >> 2, r1 = r0 + 64;
    const int ch = tid & 3;
    const uint32_t d0 = (uint32_t)(r0 * 64 + ((ch ^ ((r0 >> 1) & 3)) << 4));
    const uint32_t d1 = (uint32_t)(r1 * 64 + ((ch ^ ((r1 >> 1) & 3)) << 4));
    const int am0 = bm + r0 < M ? bm + r0 : M - 1;
    const int am1 = bm + r1 < M ? bm + r1 : M - 1;
    const uint32_t sz0 = (bm + r0 < M) ? 16u : 0u;
    const uint32_t sz1 = (bm + r1 < M) ? 16u : 0u;
    const long aro0 = (long)am0 * lda + ch * 8;
    const long aro1 = (long)am1 * lda + ch * 8;
    const long bro0 = (long)(bn + r0) * ldw + ch * 8;
    const long bro1 = (long)(bn + r1) * ldw + ch * 8;

    const int nk = K >> 5;

#define ISSUE(kc, st) do { \
    if ((kc) < nk) { \
        const int kb = (kc) * 32; \
        const uint32_t so = sb + (uint32_t)((st) * 32768); \
        CP16(so + d0,          Ahi + aro0 + kb, sz0); \
        CP16(so + d1,          Ahi + aro1 + kb, sz1); \
        CP16(so + 8192  + d0,  Alo + aro0 + kb, sz0); \
        CP16(so + 8192  + d1,  Alo + aro1 + kb, sz1); \
        CP16(so + 16384 + d0,  Bhi + bro0 + kb, 16u); \
        CP16(so + 16384 + d1,  Bhi + bro1 + kb, 16u); \
        CP16(so + 24576 + d0,  Blo + bro0 + kb, 16u); \
        CP16(so + 24576 + d1,  Blo + bro1 + kb, 16u); \
    } \
    CP_COMMIT(); \
} while (0)

    float acc[2][8][4];
#pragma unroll
    for (int mt = 0; mt < 2; mt++)
#pragma unroll
        for (int nt = 0; nt < 8; nt++)
#pragma unroll
            for (int r = 0; r < 4; r++) acc[mt][nt][r] = 0.f;

    ISSUE(0, 0);
    ISSUE(1, 1);

    for (int kc = 0; kc < nk; kc++) {
        CP_WAIT1();
        __syncthreads();
        ISSUE(kc + 2, (kc + 2) % 3);

        const uint32_t so = sb + (uint32_t)((kc % 3) * 32768);
#pragma unroll
        for (int ks = 0; ks < 2; ks++) {
            uint32_t ahi[2][4], alo[2][4];
#pragma unroll
            for (int mt = 0; mt < 2; mt++) {
                int row = wm * 32 + mt * 16 + (lane & 7) + ((lane >> 3) & 1) * 8;
                int c = 2 * ks + (lane >> 4);
                uint32_t off = (uint32_t)(row * 64 + ((c ^ ((row >> 1) & 3)) << 4));
                ldmx4(ahi[mt], so + off);
                ldmx4(alo[mt], so + 8192 + off);
            }
            uint32_t bhi[8][2], blo[8][2];
#pragma unroll
            for (int np = 0; np < 4; np++) {
                int row = wn * 64 + np * 16 + (lane & 7) + (lane >> 4) * 8;
                int c = 2 * ks + ((lane >> 3) & 1);
                uint32_t off = (uint32_t)(row * 64 + ((c ^ ((row >> 1) & 3)) << 4));
                uint32_t t[4];
                ldmx4(t, so + 16384 + off);
                bhi[2*np][0] = t[0]; bhi[2*np][1] = t[1];
                bhi[2*np+1][0] = t[2]; bhi[2*np+1][1] = t[3];
                ldmx4(t, so + 24576 + off);
                blo[2*np][0] = t[0]; blo[2*np][1] = t[1];
                blo[2*np+1][0] = t[2]; blo[2*np+1][1] = t[3];
            }
#pragma unroll
            for (int mt = 0; mt < 2; mt++)
#pragma unroll
                for (int nt = 0; nt < 8; nt++) {
                    mma_bf16(acc[mt][nt], ahi[mt], bhi[nt][0], bhi[nt][1]);
                    mma_bf16(acc[mt][nt], ahi[mt], blo[nt][0], blo[nt][1]);
                    mma_bf16(acc[mt][nt], alo[mt], bhi[nt][0], bhi[nt][1]);
                }
        }
    }
#undef ISSUE

    // ---------------- epilogue ----------------
#pragma unroll
    for (int mt = 0; mt < 2; mt++) {
        int rb = bm + wm * 32 + mt * 16 + (lane >> 2);
#pragma unroll
        for (int nt = 0; nt < 8; nt++) {
            int n0 = bn + wn * 64 + nt * 8 + (lane & 3) * 2;
            float b0 = bias[n0], b1 = bias[n0 + 1];
#pragma unroll
            for (int half = 0; half < 2; half++) {
                int r = rb + half * 8;
                if (r >= M) continue;
                float v0 = acc[mt][nt][half * 2 + 0] + b0;
                float v1 = acc[mt][nt][half * 2 + 1] + b1;
                if (EPI == 1) {
                    v0 = fmaxf(v0, 0.f); v1 = fmaxf(v1, 0.f);
                    __nv_bfloat16 h0 = __float2bfloat16_rn(v0);
                    __nv_bfloat16 h1 = __float2bfloat16_rn(v1);
                    long p = (long)r * ldc + n0;
                    *(__nv_bfloat162*)(Chi + p) = __halves2bfloat162(h0, h1);
                    *(__nv_bfloat162*)(Clo + p) = __halves2bfloat162(
                        __float2bfloat16_rn(v0 - __bfloat162float(h0)),
                        __float2bfloat16_rn(v1 - __bfloat162float(h1)));
                } else if (EPI == 2) {
                    float* base = C; int nn = n0;
                    if (nn >= 256) { base = C2; nn -= 256; }
                    int q = r >> 3, bb = r & 7, hh = nn >> 5, d = nn & 31;
                    float* p = base + (((long)(bb * NH + hh)) * NQ + q) * DH + d;
                    p[0] = v0; p[1] = v1;
                } else {
                    if (EPI == 3 && mask[(long)blockIdx.z * mOff + r]) { v0 = 0.f; v1 = 0.f; }
                    float* p = C + (long)r * ldc + n0;
                    p[0] = v0; p[1] = v1;
                }
            }
        }
    }
}

static inline void launch_mma(int epi,
    const __nv_bfloat16* Ahi, const __nv_bfloat16* Alo, int lda, long aOff,
    const __nv_bfloat16* Bhi, const __nv_bfloat16* Blo, int ldw, const float* bias,
    const __nv_bfloat16* W2hi, const __nv_bfloat16* W2lo, const float* bias2, int Nsplit,
    float* C, float* C2, __nv_bfloat16* Chi, __nv_bfloat16* Clo, int ldc, long cOff,
    int M, int N, int K, int nz,
    const unsigned char* mask, long mOff, cudaStream_t st)
{
    dim3 grid(N / 128, (M + 127) / 128, nz);
    const int SMEM = 3 * 32768;
#define LM(E) do { \
    cudaFuncSetAttribute(mma_gemm<E>, cudaFuncAttributeMaxDynamicSharedMemorySize, SMEM); \
    mma_gemm<E><<<grid,256,SMEM,st>>>(Ahi,Alo,lda,aOff,Bhi,Blo,ldw,bias,W2hi,W2lo,bias2,Nsplit, \
                                      C,C2,Chi,Clo,ldc,cOff,M,K,mask,mOff); } while (0)
    switch (epi) {
        case 0: LM(0); break;
        case 1: LM(1); break;
        case 2: LM(2); break;
        case 3: LM(3); break;
    }
#undef LM
}

// ---------------- converts ----------------
__global__ void cvt_kernel(const float* __restrict__ src,
                           __nv_bfloat16* __restrict__ hi, __nv_bfloat16* __restrict__ lo,
                           long n4)
{
    long i = (long)blockIdx.x * blockDim.x + threadIdx.x;
    if (i >= n4) return;
    float4 v = ((const float4*)src)[i];
    unsigned h[2], l[2];
    split8(&v.x, h, l);
    ((uint2*)hi)[i] = make_uint2(h[0], h[1]);
    ((uint2*)lo)[i] = make_uint2(l[0], l[1]);
}

struct WDesc { const float* src[8]; long off[8]; int n4[8]; };
__global__ void cvt_w_kernel(WDesc d, __nv_bfloat16* __restrict__ hi, __nv_bfloat16* __restrict__ lo)
{
    int w = blockIdx.y;
    int i = blockIdx.x * blockDim.x + threadIdx.x;
    if (i >= d.n4[w]) return;
    float4 v = ((const float4*)d.src[w])[i];
    unsigned h[2], l[2];
    split8(&v.x, h, l);
    ((uint2*)(hi + d.off[w]))[i] = make_uint2(h[0], h[1]);
    ((uint2*)(lo + d.off[w]))[i] = make_uint2(l[0], l[1]);
}

// fused: qb = tgt+mask planes, tg = tgt planes (one read of tgt)
__global__ void add_cvt2_kernel(const float* __restrict__ a, const float* __restrict__ b,
                                __nv_bfloat16* __restrict__ qhi, __nv_bfloat16* __restrict__ qlo,
                                __nv_bfloat16* __restrict__ thi, __nv_bfloat16* __restrict__ tlo)
{
    int i = blockIdx.x * 256 + threadIdx.x;
    if (i >= TOKF/4) return;
    float4 x = ((const float4*)a)[i], y = ((const float4*)b)[i];
    unsigned h[2], l[2];
    split8(&x.x, h, l);
    ((uint2*)thi)[i] = make_uint2(h[0], h[1]);
    ((uint2*)tlo)[i] = make_uint2(l[0], l[1]);
    float v[4] = {x.x+y.x, x.y+y.y, x.z+y.z, x.w+y.w};
    split8(v, h, l);
    ((uint2*)qhi)[i] = make_uint2(h[0], h[1]);
    ((uint2*)qlo)[i] = make_uint2(l[0], l[1]);
}

// query2 planes in (b,q,d) layout from tgt2 (q,b,d) + mask
__global__ void permadd_cvt_kernel(const float* __restrict__ t2, const float* __restrict__ msk,
                                   __nv_bfloat16* __restrict__ hi, __nv_bfloat16* __restrict__ lo)
{
    int i = blockIdx.x * 256 + threadIdx.x;
    if (i >= TOKF/4) return;
    int d4 = i & 63;
    int t = i >> 6;
    int q = t >> 3, b = t & 7;
    float4 x = ((const float4*)t2)[i], y = ((const float4*)msk)[i];
    float v[4] = {x.x+y.x, x.y+y.y, x.z+y.z, x.w+y.w};
    unsigned h[2], l[2];
    split8(v, h, l);
    long o = ((long)(b*NQ + q) << 6) + d4;
    ((uint2*)hi)[o] = make_uint2(h[0], h[1]);
    ((uint2*)lo)[o] = make_uint2(l[0], l[1]);
}

// ---------------- residual + layernorm (optional hi/lo plane out) ----------------
__global__ void __launch_bounds__(256) ln_kernel(
    const float* __restrict__ A, const float* __restrict__ B, int bBQ,
    const float* __restrict__ g, const float* __restrict__ be,
    float* __restrict__ out,
    __nv_bfloat16* __restrict__ ohi, __nv_bfloat16* __restrict__ olo)
{
    int t = blockIdx.x * 8 + (threadIdx.x >> 5);
    int lane = threadIdx.x & 31;
    if (t >= NTOK) return;
    const float* ap = A + (long)t * DIM + lane*8;
    long bo;
    if (bBQ) { int q = t >> 3, b = t & 7; bo = (long)(b*NQ + q) * DIM; }
    else     { bo = (long)t * DIM; }
    const float* bp = B + bo + lane*8;

    float4 x0 = *(const float4*)ap,      x1 = *(const float4*)(ap + 4);
    float4 y0 = *(const float4*)bp,      y1 = *(const float4*)(bp + 4);
    float v[8] = {x0.x+y0.x, x0.y+y0.y, x0.z+y0.z, x0.w+y0.w,
                  x1.x+y1.x, x1.y+y1.y, x1.z+y1.z, x1.w+y1.w};
    float s = 0.f;
#pragma unroll
    for (int i = 0; i < 8; i++) s += v[i];
#pragma unroll
    for (int o = 16; o; o >>= 1) s += __shfl_xor_sync(0xffffffffu, s, o);
    float mu = s * (1.f/256.f);
    float s2 = 0.f;
#pragma unroll
    for (int i = 0; i < 8; i++) { float d = v[i] - mu; s2 += d*d; }
#pragma unroll
    for (int o = 16; o; o >>= 1) s2 += __shfl_xor_sync(0xffffffffu, s2, o);
    float inv = rsqrtf(s2 * (1.f/256.f) + 1e-5f);
    int c0 = lane*8;
    float* op = out + (long)t * DIM + c0;
    float r[8];
#pragma unroll
    for (int i = 0; i < 8; i++) {
        r[i] = (v[i] - mu) * inv * g[c0+i] + be[c0+i];
        op[i] = r[i];
    }
    if (ohi) {
        unsigned h[2], l[2];
        split8(r, h, l);
        unsigned h2[2], l2[2];
        split8(r + 4, h2, l2);
        long o4 = ((long)t * DIM + c0) >> 2;
        ((uint2*)ohi)[o4]   = make_uint2(h[0], h[1]);
        ((uint2*)ohi)[o4+1] = make_uint2(h2[0], h2[1]);
        ((uint2*)olo)[o4]   = make_uint2(l[0], l[1]);
        ((uint2*)olo)[o4+1] = make_uint2(l2[0], l2[1]);
    }
}

// ---------------- fused self-attention (writes hi/lo planes) ----------------
__global__ void __launch_bounds__(256) attn_kernel(
    const float* __restrict__ qh, const float* __restrict__ kh,
    const float* __restrict__ vh,
    __nv_bfloat16* __restrict__ sah, __nv_bfloat16* __restrict__ sal)
{
    extern __shared__ float smf[];
    const int bh   = blockIdx.x >> 1;
    const int half = blockIdx.x & 1;
    const int b = bh >> 3, h = bh & 7;
    float* Ks = smf;
    float* Vs = Ks + 300*36;
    float* Qs = Vs + 300*36;
    float* Ps = Qs + 150*32;

    const float scale = 0.17677669529663687f;
    const float* Kg = kh + (long)bh * NQ * DH;
    const float* Vg = vh + (long)bh * NQ * DH;
    const float* Qg = qh + (long)bh * NQ * DH + (long)half * 150 * DH;
    const int tid = threadIdx.x;

    for (int i = tid; i < 2400; i += 256) {
        int r = i >> 3, c4 = (i & 7) << 2;
        float4 kv = *(const float4*)(Kg + r*32 + c4);
        float4 vv = *(const float4*)(Vg + r*32 + c4);
        *(float4*)(Ks + r*36 + c4) = kv;
        *(float4*)(Vs + r*36 + c4) = vv;
    }
    for (int i = tid; i < 1200; i += 256) {
        int r = i >> 3, c4 = (i & 7) << 2;
        float4 qv = *(const float4*)(Qg + r*32 + c4);
        qv.x *= scale; qv.y *= scale; qv.z *= scale; qv.w *= scale;
        *(float4*)(Qs + r*32 + c4) = qv;
    }
    __syncthreads();

    const int warp = tid >> 5, lane = tid & 31;
    float* Pw = Ps + warp * 320;

    for (int q = warp; q < 150; q += 8) {
        float4 qr[8];
#pragma unroll
        for (int d4 = 0; d4 < 8; d4++) qr[d4] = *(const float4*)(Qs + q*32 + d4*4);

        float sc[10];
#pragma unroll
        for (int j = 0; j < 10; j++) {
            int k = j*32 + lane;
            float s = -1e30f;
            if (k < 300) {
                s = 0.f;
#pragma unroll
                for (int d4 = 0; d4 < 8; d4++) {
                    float4 kv = *(const float4*)(Ks + k*36 + d4*4);
                    s = fmaf(qr[d4].x, kv.x, s);
                    s = fmaf(qr[d4].y, kv.y, s);
                    s = fmaf(qr[d4].z, kv.z, s);
                    s = fmaf(qr[d4].w, kv.w, s);
                }
            }
            sc[j] = s;
        }
        float m = sc[0];
#pragma unroll
        for (int j = 1; j < 10; j++) m = fmaxf(m, sc[j]);
#pragma unroll
        for (int o = 16; o; o >>= 1) m = fmaxf(m, __shfl_xor_sync(0xffffffffu, m, o));
        float sum = 0.f;
#pragma unroll
        for (int j = 0; j < 10; j++) { sc[j] = expf(sc[j] - m); sum += sc[j]; }
#pragma unroll
        for (int o = 16; o; o >>= 1) sum += __shfl_xor_sync(0xffffffffu, sum, o);
        float inv = 1.f / sum;
#pragma unroll
        for (int j = 0; j < 10; j++) Pw[j*32 + lane] = sc[j] * inv;
        __syncwarp();

        float acc = 0.f;
#pragma unroll 4
        for (int k = 0; k < 300; k++)
            acc = fmaf(Pw[k], Vs[k*36 + lane], acc);

        int qg = half*150 + q;
        long o = ((long)(qg*BSZ + b)) * DIM + h*DH + lane;
        __nv_bfloat16 hi = __float2bfloat16_rn(acc);
        sah[o] = hi;
        sal[o] = __float2bfloat16_rn(acc - __bfloat162float(hi));
        __syncwarp();
    }
}

// ---------------- multi-scale deformable sampling (writes hi/lo planes) ----------------
__global__ void __launch_bounds__(256) deform_kernel(
    const float* __restrict__ offaw,
    const float* __restrict__ bbox, const float* __restrict__ value,
    const int* __restrict__ spatial, const int* __restrict__ lstart,
    __nv_bfloat16* __restrict__ cah, __nv_bfloat16* __restrict__ cal)
{
    __shared__ float s_w[8][32][4];
    __shared__ int   s_i[8][32][4];
    int bq = blockIdx.x;
    int b = bq / NQ, q = bq - b*NQ;
    int warp = threadIdx.x >> 5, lane = threadIdx.x & 31;

    const float* tok = offaw + (long)bq * 768;
    float a = tok[512 + warp*32 + lane];
    float m = a;
#pragma unroll
    for (int o = 16; o; o >>= 1) m = fmaxf(m, __shfl_xor_sync(0xffffffffu, m, o));
    float e = expf(a - m);
    float s = e;
#pragma unroll
    for (int o = 16; o; o >>= 1) s += __shfl_xor_sync(0xffffffffu, s, o);
    float p = e / s;

    float ox = tok[warp*64 + lane*2];
    float oy = tok[warp*64 + lane*2 + 1];
    const float* rb = bbox + ((long)q*BSZ + b)*4;
    float r0 = rb[0], r1 = rb[1], r2 = rb[2], r3 = rb[3];

    int lvl = lane >> 3;
    int H = spatial[lvl*2], W = spatial[lvl*2 + 1], ls = lstart[lvl];
    float Wf = (float)W, Hf = (float)H;
    float x = (r0 + ox*0.0625f*r2) * Wf - 0.5f;
    float y = (r1 + oy*0.0625f*r3) * Hf - 0.5f;
    float x0 = floorf(x), y0 = floorf(y);
    float fx = x - x0, fy = y - y0;

#pragma unroll
    for (int c = 0; c < 4; c++) {
        float xi = x0 + (float)(c & 1);
        float yi = y0 + (float)(c >> 1);
        float wgt = ((c & 1) ? fx : 1.f - fx) * ((c >> 1) ? fy : 1.f - fy);
        bool valid = (xi >= 0.f) && (xi < Wf) && (yi >= 0.f) && (yi < Hf);
        int xc = (int)fminf(fmaxf(xi, 0.f), Wf - 1.f);
        int yc = (int)fminf(fmaxf(yi, 0.f), Hf - 1.f);
        s_i[warp][lane][c] = ls + yc*W + xc;
        s_w[warp][lane][c] = valid ? wgt * p : 0.f;
    }
    __syncwarp();

    const float* vb = value + (long)b * STOT * DIM + warp*DH + lane;
    float acc = 0.f;
    for (int lp = 0; lp < 32; lp++) {
#pragma unroll
        for (int c = 0; c < 4; c++) {
            float wgt = s_w[warp][lp][c];
            if (wgt != 0.f)
                acc = fmaf(wgt, vb[(long)s_i[warp][lp][c] << 8], acc);
        }
    }
    long o = (long)bq*DIM + warp*DH + lane;
    __nv_bfloat16 hi = __float2bfloat16_rn(acc);
    cah[o] = hi;
    cal[o] = __float2bfloat16_rn(acc - __bfloat162float(hi));
}

// ---------------- host orchestration ----------------
extern "C" void kernel_launch(void* const* d_in, const int* in_sizes, int n_in,
                              void* d_out, int out_size)
{
    const float* tgt        = (const float*)d_in[0];
    const float* qmask      = (const float*)d_in[1];
    const float* bbox       = (const float*)d_in[2];
    const float* memory     = (const float*)d_in[4];
    const float* in_proj_w  = (const float*)d_in[5];
    const float* in_proj_b  = (const float*)d_in[6];
    const float* out_sa_w   = (const float*)d_in[7];
    const float* out_sa_b   = (const float*)d_in[8];
    const float* norm2_g    = (const float*)d_in[9];
    const float* norm2_b    = (const float*)d_in[10];
    const float* value_w    = (const float*)d_in[11];
    const float* value_b    = (const float*)d_in[12];
    const float* off_w      = (const float*)d_in[13];
    const float* off_b      = (const float*)d_in[14];
    const float* aw_w       = (const float*)d_in[15];
    const float* aw_b       = (const float*)d_in[16];
    const float* out_ca_w   = (const float*)d_in[17];
    const float* out_ca_b   = (const float*)d_in[18];
    const float* norm1_g    = (const float*)d_in[19];
    const float* norm1_b    = (const float*)d_in[20];
    const float* lin1_w     = (const float*)d_in[21];
    const float* lin1_b     = (const float*)d_in[22];
    const float* lin2_w     = (const float*)d_in[23];
    const float* lin2_b     = (const float*)d_in[24];
    const float* norm3_g    = (const float*)d_in[25];
    const float* norm3_b    = (const float*)d_in[26];
    const unsigned char* pmask = (const unsigned char*)d_in[27];
    const int* spatial      = (const int*)d_in[28];
    const int* lstart       = (const int*)d_in[29];
    float* out = (float*)d_out;

    float *qhp,*khp,*vhp,*saout,*tgt2,*offb,*val,*caout,*tgt3,*f2;
    __nv_bfloat16 *memh,*meml,*wh,*wl,*qbh,*qbl,*tgh,*tgl,*sah,*sal,*q2h,*q2l,*t3h,*t3l,*f1h,*f1l,*cah,*cal;
    cudaGetSymbolAddress((void**)&qhp,   g_qh);
    cudaGetSymbolAddress((void**)&khp,   g_kh);
    cudaGetSymbolAddress((void**)&vhp,   g_vh);
    cudaGetSymbolAddress((void**)&saout, g_saout);
    cudaGetSymbolAddress((void**)&tgt2,  g_tgt2);
    cudaGetSymbolAddress((void**)&offb,  g_off);
    cudaGetSymbolAddress((void**)&val,   g_value);
    cudaGetSymbolAddress((void**)&caout, g_caout);
    cudaGetSymbolAddress((void**)&tgt3,  g_tgt3);
    cudaGetSymbolAddress((void**)&f2,    g_f2);
    cudaGetSymbolAddress((void**)&memh,  g_memh);
    cudaGetSymbolAddress((void**)&meml,  g_meml);
    cudaGetSymbolAddress((void**)&wh,    g_wh);
    cudaGetSymbolAddress((void**)&wl,    g_wl);
    cudaGetSymbolAddress((void**)&qbh,   g_qbh);
    cudaGetSymbolAddress((void**)&qbl,   g_qbl);
    cudaGetSymbolAddress((void**)&tgh,   g_tgh);
    cudaGetSymbolAddress((void**)&tgl,   g_tgl);
    cudaGetSymbolAddress((void**)&sah,   g_sah);
    cudaGetSymbolAddress((void**)&sal,   g_sal);
    cudaGetSymbolAddress((void**)&q2h,   g_q2h);
    cudaGetSymbolAddress((void**)&q2l,   g_q2l);
    cudaGetSymbolAddress((void**)&t3h,   g_t3h);
    cudaGetSymbolAddress((void**)&t3l,   g_t3l);
    cudaGetSymbolAddress((void**)&f1h,   g_f1h);
    cudaGetSymbolAddress((void**)&f1l,   g_f1l);
    cudaGetSymbolAddress((void**)&cah,   g_cah);
    cudaGetSymbolAddress((void**)&cal,   g_cal);

    // fork stream for the value path (memory convert + value GEMM)
    cudaStream_t sV;
    cudaStreamCreateWithFlags(&sV, cudaStreamNonBlocking);
    cudaEvent_t ev0, evW, evJ;
    cudaEventCreateWithFlags(&ev0, cudaEventDisableTiming);
    cudaEventCreateWithFlags(&evW, cudaEventDisableTiming);
    cudaEventCreateWithFlags(&evJ, cudaEventDisableTiming);

    // fork at the very start: sV converts memory (no deps)
    cudaEventRecord(ev0, 0);
    cudaStreamWaitEvent(sV, ev0, 0);
    cvt_kernel<<<(unsigned)(MEMN/4/256), 256, 0, sV>>>(memory, memh, meml, MEMN/4);

    // main: weight converts (value GEMM needs W_VALUE planes)
    {
        WDesc d;
        d.src[0]=in_proj_w; d.off[0]=W_INPROJ; d.n4[0]=196608/4;
        d.src[1]=out_sa_w;  d.off[1]=W_OUTSA;  d.n4[1]=65536/4;
        d.src[2]=value_w;   d.off[2]=W_VALUE;  d.n4[2]=65536/4;
        d.src[3]=off_w;     d.off[3]=W_OFF;    d.n4[3]=131072/4;
        d.src[4]=aw_w;      d.off[4]=W_AW;     d.n4[4]=65536/4;
        d.src[5]=out_ca_w;  d.off[5]=W_OUTCA;  d.n4[5]=65536/4;
        d.src[6]=lin1_w;    d.off[6]=W_LIN1;   d.n4[6]=262144/4;
        d.src[7]=lin2_w;    d.off[7]=W_LIN2;   d.n4[7]=262144/4;
        dim3 g((262144/4 + 255)/256, 8);
        cvt_w_kernel<<<g, 256>>>(d, wh, wl);
    }
    cudaEventRecord(evW, 0);
    cudaStreamWaitEvent(sV, evW, 0);

    // sV: value projection (batched over BS), pad-mask epilogue
    launch_mma(3, memh, meml, BSZ*DIM, 256, wh+W_VALUE, wl+W_VALUE, DIM, value_b,
               nullptr, nullptr, nullptr, 0,
               val, nullptr, nullptr, nullptr, DIM, (long)STOT*DIM,
               STOT, DIM, DIM, BSZ, pmask, STOT, sV);
    cudaEventRecord(evJ, sV);

    // main: SA chain
    add_cvt2_kernel<<<TOKF/4/256, 256>>>(tgt, qmask, qbh, qbl, tgh, tgl);

    launch_mma(2, qbh, qbl, DIM, 0, wh+W_INPROJ, wl+W_INPROJ, DIM, in_proj_b,
               nullptr, nullptr, nullptr, 0,
               qhp, khp, nullptr, nullptr, 0, 0, NTOK, 512, DIM, 1, nullptr, 0, 0);
    launch_mma(2, tgh, tgl, DIM, 0, wh+W_INPROJ+512*256, wl+W_INPROJ+512*256, DIM, in_proj_b+512,
               nullptr, nullptr, nullptr, 0,
               vhp, vhp, nullptr, nullptr, 0, 0, NTOK, 256, DIM, 1, nullptr, 0, 0);

    {
        int smem = (300*36*2 + 150*32 + 8*320) * 4;
        cudaFuncSetAttribute(attn_kernel, cudaFuncAttributeMaxDynamicSharedMemorySize, smem);
        attn_kernel<<<128, 256, smem>>>(qhp, khp, vhp, sah, sal);
    }

    launch_mma(0, sah, sal, DIM, 0, wh+W_OUTSA, wl+W_OUTSA, DIM, out_sa_b,
               nullptr, nullptr, nullptr, 0,
               saout, nullptr, nullptr, nullptr, DIM, 0, NTOK, 256, DIM, 1, nullptr, 0, 0);
    ln_kernel<<<NTOK/8, 256>>>(tgt, saout, 0, norm2_g, norm2_b, tgt2, nullptr, nullptr);

    permadd_cvt_kernel<<<(TOKF/4 + 255)/256, 256>>>(tgt2, qmask, q2h, q2l);

    launch_mma(0, q2h, q2l, DIM, 0, wh+W_OFF, wl+W_OFF, DIM, off_b,
               wh+W_AW, wl+W_AW, aw_b, 512,
               offb, nullptr, nullptr, nullptr, 768, 0, NTOK, 768, DIM, 1, nullptr, 0, 0);

    // join: deform needs val (sV) + offb (main)
    cudaStreamWaitEvent(0, evJ, 0);
    deform_kernel<<<NTOK, 256>>>(offb, bbox, val, spatial, lstart, cah, cal);

    launch_mma(0, cah, cal, DIM, 0, wh+W_OUTCA, wl+W_OUTCA, DIM, out_ca_b,
               nullptr, nullptr, nullptr, 0,
               caout, nullptr, nullptr, nullptr, DIM, 0, NTOK, 256, DIM, 1, nullptr, 0, 0);
    ln_kernel<<<NTOK/8, 256>>>(tgt2, caout, 1, norm1_g, norm1_b, tgt3, t3h, t3l);

    launch_mma(1, t3h, t3l, DIM, 0, wh+W_LIN1, wl+W_LIN1, DIM, lin1_b,
               nullptr, nullptr, nullptr, 0,
               nullptr, nullptr, f1h, f1l, DFF, 0, NTOK, DFF, DIM, 1, nullptr, 0, 0);
    launch_mma(0, f1h, f1l, DFF, 0, wh+W_LIN2, wl+W_LIN2, DFF, lin2_b,
               nullptr, nullptr, nullptr, 0,
               f2, nullptr, nullptr, nullptr, DIM, 0, NTOK, 256, DFF, 1, nullptr, 0, 0);
    ln_kernel<<<NTOK/8, 256>>>(tgt3, f2, 0, norm3_g, norm3_b, out, nullptr, nullptr);
}

// round 7
// speedup vs baseline: 1.0851x; 1.0625x over previous
#include <cuda_runtime.h>
#include <cuda_bf16.h>
#include <math.h>
#include <cstdint>

// ---------------- problem constants ----------------
#define NQ   300
#define BSZ  8
#define DIM  256
#define NH   8
#define DH   32
#define DFF  1024
#define STOT 13294
#define NTOK (NQ*BSZ)          // 2400
#define TOKF (NTOK*DIM)        // 614400

// ---------------- scratch (static device globals; no allocations) ----------------
__device__ float g_qbuf [TOKF];
__device__ float g_qh   [TOKF];
__device__ float g_kh   [TOKF];
__device__ float g_vh   [TOKF];
__device__ float g_sain [TOKF];
__device__ float g_saout[TOKF];
__device__ float g_tgt2 [TOKF];
__device__ float g_q2   [TOKF];
__device__ float g_off  [NTOK*768];
__device__ float g_value[(long)BSZ*STOT*DIM];
__device__ float g_cain [TOKF];
__device__ float g_caout[TOKF];
__device__ float g_tgt3 [TOKF];
__device__ float g_f1   [NTOK*DFF];
__device__ float g_f2   [TOKF];

// ---------------- helpers ----------------
__device__ __forceinline__ uint32_t smem_u32(const void* p) {
    uint32_t a;
    asm("{ .reg .u64 t; cvta.to.shared.u64 t, %1; cvt.u32.u64 %0, t; }" : "=r"(a) : "l"(p));
    return a;
}
__device__ __forceinline__ unsigned pk2(__nv_bfloat16 a, __nv_bfloat16 b) {
    __nv_bfloat162 t = __halves2bfloat162(a, b);
    return *reinterpret_cast<unsigned*>(&t);
}
__device__ __forceinline__ void mma_bf16(float* d, const uint32_t* a, uint32_t b0, uint32_t b1) {
    asm volatile(
        "mma.sync.aligned.m16n8k16.row.col.f32.bf16.bf16.f32 "
        "{%0,%1,%2,%3}, {%4,%5,%6,%7}, {%8,%9}, {%0,%1,%2,%3};"
        : "+f"(d[0]), "+f"(d[1]), "+f"(d[2]), "+f"(d[3])
        : "r"(a[0]), "r"(a[1]), "r"(a[2]), "r"(a[3]), "r"(b0), "r"(b1));
}
__device__ __forceinline__ void ldmx4(uint32_t* r, uint32_t addr) {
    asm volatile("ldmatrix.sync.aligned.m8n8.x4.shared.b16 {%0,%1,%2,%3}, [%4];"
                 : "=r"(r[0]), "=r"(r[1]), "=r"(r[2]), "=r"(r[3]) : "r"(addr));
}
__device__ __forceinline__ void cvt_hilo(float4 v, uint2& hi, uint2& lo) {
    __nv_bfloat16 h0 = __float2bfloat16_rn(v.x), h1 = __float2bfloat16_rn(v.y);
    __nv_bfloat16 h2 = __float2bfloat16_rn(v.z), h3 = __float2bfloat16_rn(v.w);
    __nv_bfloat16 l0 = __float2bfloat16_rn(v.x - __bfloat162float(h0));
    __nv_bfloat16 l1 = __float2bfloat16_rn(v.y - __bfloat162float(h1));
    __nv_bfloat16 l2 = __float2bfloat16_rn(v.z - __bfloat162float(h2));
    __nv_bfloat16 l3 = __float2bfloat16_rn(v.w - __bfloat162float(h3));
    hi = make_uint2(pk2(h0, h1), pk2(h2, h3));
    lo = make_uint2(pk2(l0, l1), pk2(l2, l3));
}

// ============ mma.sync bf16 3-term GEMM: C = A(MxK)*W(NxK)^T + bias ============
// fp32 inputs, in-register hi/lo split. CTA 64x128, 256 thr, 8 warps of 32x32.
// K chunks of 32, 2-stage smem ping-pong (one sync per chunk).
// EPI: 0 plain, 1 relu, 2 head-permute [(b*NH+h)][q][d] (C2 for n>=256),
//      3 pad-mask zero (batched). Nsplit: switch W/bias to W2/bias2 at column Nsplit.
#define STG 24576

template<int EPI>
__global__ void __launch_bounds__(256, 2) mma_gemm(
    const float* __restrict__ A, int lda, long aOff,
    const float* __restrict__ W, int ldw,
    const float* __restrict__ bias,
    const float* __restrict__ W2, const float* __restrict__ bias2, int Nsplit,
    float* __restrict__ C, float* __restrict__ C2, int ldc, long cOff,
    int M, int K,
    const unsigned char* __restrict__ mask, long mOff)
{
    extern __shared__ __align__(128) unsigned char sm[];
    const uint32_t sb = smem_u32(sm);
    const int tid = threadIdx.x;
    const int bm = blockIdx.y * 64;
    const int bn = blockIdx.x * 128;
    A += (long)blockIdx.z * aOff;
    C += (long)blockIdx.z * cOff;
    if (Nsplit && bn >= Nsplit) { W = W2 - (long)Nsplit * ldw; bias = bias2 - Nsplit; }

    const int warp = tid >> 5, lane = tid & 31;
    const int wm = warp & 1, wn = warp >> 1;

    int arow[2], akq[2]; bool agd[2]; const float* aptr[2];
#pragma unroll
    for (int j = 0; j < 2; j++) {
        int i = tid + j * 256;
        arow[j] = i >> 3; akq[j] = i & 7;
        agd[j] = (bm + arow[j]) < M;
        aptr[j] = A + (long)(bm + arow[j]) * lda + akq[j] * 4;
    }
    int brow[4], bkq[4]; const float* bptr[4];
#pragma unroll
    for (int j = 0; j < 4; j++) {
        int i = tid + j * 256;
        brow[j] = i >> 3; bkq[j] = i & 7;
        bptr[j] = W + (long)(bn + brow[j]) * ldw + bkq[j] * 4;
    }
    uint32_t asw[2], bsw[4];
#pragma unroll
    for (int j = 0; j < 2; j++)
        asw[j] = (uint32_t)(arow[j] * 64 + (((akq[j] >> 1) ^ ((arow[j] >> 1) & 3)) << 4) + (akq[j] & 1) * 8);
#pragma unroll
    for (int j = 0; j < 4; j++)
        bsw[j] = (uint32_t)(brow[j] * 64 + (((bkq[j] >> 1) ^ ((brow[j] >> 1) & 3)) << 4) + (bkq[j] & 1) * 8);

    float acc[2][4][4];
#pragma unroll
    for (int mt = 0; mt < 2; mt++)
#pragma unroll
        for (int nt = 0; nt < 4; nt++)
#pragma unroll
            for (int r = 0; r < 4; r++) acc[mt][nt][r] = 0.f;

    const int nk = K >> 5;
    float4 av[2], bv[4];

    // load + stage chunk 0
#pragma unroll
    for (int j = 0; j < 2; j++)
        av[j] = agd[j] ? *(const float4*)(aptr[j]) : make_float4(0.f,0.f,0.f,0.f);
#pragma unroll
    for (int j = 0; j < 4; j++) bv[j] = *(const float4*)(bptr[j]);
#pragma unroll
    for (int j = 0; j < 2; j++) {
        uint2 hi, lo; cvt_hilo(av[j], hi, lo);
        *(uint2*)(sm + asw[j]) = hi;
        *(uint2*)(sm + 4096 + asw[j]) = lo;
    }
#pragma unroll
    for (int j = 0; j < 4; j++) {
        uint2 hi, lo; cvt_hilo(bv[j], hi, lo);
        *(uint2*)(sm + 8192 + bsw[j]) = hi;
        *(uint2*)(sm + 16384 + bsw[j]) = lo;
    }
    __syncthreads();

    for (int kc = 0; kc < nk; kc++) {
        const int st = kc & 1;
        const uint32_t so = sb + (uint32_t)(st * STG);
        const bool more = (kc + 1) < nk;

        if (more) {
            int kb = (kc + 1) * 32;
#pragma unroll
            for (int j = 0; j < 2; j++)
                av[j] = agd[j] ? *(const float4*)(aptr[j] + kb) : make_float4(0.f,0.f,0.f,0.f);
#pragma unroll
            for (int j = 0; j < 4; j++) bv[j] = *(const float4*)(bptr[j] + kb);
        }

#pragma unroll
        for (int ks = 0; ks < 2; ks++) {
            uint32_t ahi[2][4], alo[2][4];
#pragma unroll
            for (int mt = 0; mt < 2; mt++) {
                int row = wm * 32 + mt * 16 + (lane & 7) + ((lane >> 3) & 1) * 8;
                int c = 2 * ks + (lane >> 4);
                uint32_t off = (uint32_t)(row * 64 + ((c ^ ((row >> 1) & 3)) << 4));
                ldmx4(ahi[mt], so + off);
                ldmx4(alo[mt], so + 4096 + off);
            }
            uint32_t bhi[4][2], blo[4][2];
#pragma unroll
            for (int np = 0; np < 2; np++) {
                int row = wn * 32 + np * 16 + (lane & 7) + (lane >> 4) * 8;
                int c = 2 * ks + ((lane >> 3) & 1);
                uint32_t off = (uint32_t)(row * 64 + ((c ^ ((row >> 1) & 3)) << 4));
                uint32_t t[4];
                ldmx4(t, so + 8192 + off);
                bhi[2*np][0] = t[0]; bhi[2*np][1] = t[1];
                bhi[2*np+1][0] = t[2]; bhi[2*np+1][1] = t[3];
                ldmx4(t, so + 16384 + off);
                blo[2*np][0] = t[0]; blo[2*np][1] = t[1];
                blo[2*np+1][0] = t[2]; blo[2*np+1][1] = t[3];
            }
#pragma unroll
            for (int mt = 0; mt < 2; mt++)
#pragma unroll
                for (int nt = 0; nt < 4; nt++) {
                    mma_bf16(acc[mt][nt], ahi[mt], bhi[nt][0], bhi[nt][1]);
                    mma_bf16(acc[mt][nt], ahi[mt], blo[nt][0], blo[nt][1]);
                    mma_bf16(acc[mt][nt], alo[mt], bhi[nt][0], bhi[nt][1]);
                }
        }

        if (more) {
            const uint32_t po = (uint32_t)((st ^ 1) * STG);
#pragma unroll
            for (int j = 0; j < 2; j++) {
                uint2 hi, lo; cvt_hilo(av[j], hi, lo);
                *(uint2*)(sm + po + asw[j]) = hi;
                *(uint2*)(sm + po + 4096 + asw[j]) = lo;
            }
#pragma unroll
            for (int j = 0; j < 4; j++) {
                uint2 hi, lo; cvt_hilo(bv[j], hi, lo);
                *(uint2*)(sm + po + 8192 + bsw[j]) = hi;
                *(uint2*)(sm + po + 16384 + bsw[j]) = lo;
            }
        }
        __syncthreads();
    }

    // ---------------- epilogue ----------------
#pragma unroll
    for (int mt = 0; mt < 2; mt++) {
        int r0 = bm + wm * 32 + mt * 16 + (lane >> 2);
#pragma unroll
        for (int nt = 0; nt < 4; nt++) {
            int n0 = bn + wn * 32 + nt * 8 + (lane & 3) * 2;
            float b0 = bias[n0], b1 = bias[n0 + 1];
#pragma unroll
            for (int half = 0; half < 2; half++) {
                int r = r0 + half * 8;
                if (r >= M) continue;
                float v0 = acc[mt][nt][half * 2 + 0] + b0;
                float v1 = acc[mt][nt][half * 2 + 1] + b1;
                if (EPI == 1) { v0 = fmaxf(v0, 0.f); v1 = fmaxf(v1, 0.f); }
                if (EPI == 3) {
                    if (mask[(long)blockIdx.z * mOff + r]) { v0 = 0.f; v1 = 0.f; }
                }
                if (EPI == 2) {
                    float* base = C; int nn = n0;
                    if (C2 && nn >= 256) { base = C2; nn -= 256; }
                    int q = r >> 3, bb = r & 7, hh = nn >> 5, d = nn & 31;
                    float* p = base + (((long)(bb * NH + hh)) * NQ + q) * DH + d;
                    p[0] = v0; p[1] = v1;
                } else {
                    float* p = C + (long)r * ldc + n0;
                    p[0] = v0; p[1] = v1;
                }
            }
        }
    }
}

static inline void launch_mma(int epi,
    const float* A, int lda, long aOff,
    const float* W, int ldw, const float* bias,
    const float* W2, const float* bias2, int Nsplit,
    float* C, float* C2, int ldc, long cOff,
    int M, int N, int K, int nz,
    const unsigned char* mask, long mOff, cudaStream_t st)
{
    dim3 grid(N / 128, (M + 63) / 64, nz);
    const int SMEM = 2 * STG;
#define LM(E) do { \
    cudaFuncSetAttribute(mma_gemm<E>, cudaFuncAttributeMaxDynamicSharedMemorySize, SMEM); \
    mma_gemm<E><<<grid,256,SMEM,st>>>(A,lda,aOff,W,ldw,bias,W2,bias2,Nsplit,C,C2,ldc,cOff,M,K,mask,mOff); } while (0)
    switch (epi) {
        case 0: LM(0); break;
        case 1: LM(1); break;
        case 2: LM(2); break;
        case 3: LM(3); break;
    }
#undef LM
}

// ---------------- elementwise ----------------
__global__ void add_kernel(const float* __restrict__ a, const float* __restrict__ b,
                           float* __restrict__ o, int n4)
{
    int i = blockIdx.x * blockDim.x + threadIdx.x;
    if (i < n4) {
        float4 x = ((const float4*)a)[i], y = ((const float4*)b)[i];
        ((float4*)o)[i] = make_float4(x.x+y.x, x.y+y.y, x.z+y.z, x.w+y.w);
    }
}

__global__ void permadd_kernel(const float* __restrict__ t2, const float* __restrict__ msk,
                               float* __restrict__ q2)
{
    int i = blockIdx.x * 256 + threadIdx.x;   // over TOKF/4 float4s
    if (i >= TOKF/4) return;
    int d4 = i & 63;
    int t = i >> 6;
    int q = t >> 3, b = t & 7;
    float4 x = ((const float4*)t2)[i], y = ((const float4*)msk)[i];
    ((float4*)q2)[((long)(b*NQ + q) << 6) + d4] = make_float4(x.x+y.x, x.y+y.y, x.z+y.z, x.w+y.w);
}

// ---------------- residual + layernorm ----------------
__global__ void __launch_bounds__(256) ln_kernel(
    const float* __restrict__ A, const float* __restrict__ B, int bBQ,
    const float* __restrict__ g, const float* __restrict__ be,
    float* __restrict__ out)
{
    int t = blockIdx.x * 8 + (threadIdx.x >> 5);
    int lane = threadIdx.x & 31;
    if (t >= NTOK) return;
    const float* ap = A + (long)t * DIM + lane*8;
    long bo;
    if (bBQ) { int q = t >> 3, b = t & 7; bo = (long)(b*NQ + q) * DIM; }
    else     { bo = (long)t * DIM; }
    const float* bp = B + bo + lane*8;

    float4 x0 = *(const float4*)ap,      x1 = *(const float4*)(ap + 4);
    float4 y0 = *(const float4*)bp,      y1 = *(const float4*)(bp + 4);
    float v[8] = {x0.x+y0.x, x0.y+y0.y, x0.z+y0.z, x0.w+y0.w,
                  x1.x+y1.x, x1.y+y1.y, x1.z+y1.z, x1.w+y1.w};
    float s = 0.f;
#pragma unroll
    for (int i = 0; i < 8; i++) s += v[i];
#pragma unroll
    for (int o = 16; o; o >>= 1) s += __shfl_xor_sync(0xffffffffu, s, o);
    float mu = s * (1.f/256.f);
    float s2 = 0.f;
#pragma unroll
    for (int i = 0; i < 8; i++) { float d = v[i] - mu; s2 += d*d; }
#pragma unroll
    for (int o = 16; o; o >>= 1) s2 += __shfl_xor_sync(0xffffffffu, s2, o);
    float inv = rsqrtf(s2 * (1.f/256.f) + 1e-5f);
    int c0 = lane*8;
    float* op = out + (long)t * DIM + c0;
#pragma unroll
    for (int i = 0; i < 8; i++)
        op[i] = (v[i] - mu) * inv * g[c0+i] + be[c0+i];
}

// ---------------- fused self-attention ----------------
__global__ void __launch_bounds__(256) attn_kernel(
    const float* __restrict__ qh, const float* __restrict__ kh,
    const float* __restrict__ vh, float* __restrict__ sa_in)
{
    extern __shared__ float smf[];
    const int bh   = blockIdx.x >> 1;
    const int half = blockIdx.x & 1;
    const int b = bh >> 3, h = bh & 7;
    float* Ks = smf;
    float* Vs = Ks + 300*36;
    float* Qs = Vs + 300*36;
    float* Ps = Qs + 150*32;

    const float scale = 0.17677669529663687f;
    const float* Kg = kh + (long)bh * NQ * DH;
    const float* Vg = vh + (long)bh * NQ * DH;
    const float* Qg = qh + (long)bh * NQ * DH + (long)half * 150 * DH;
    const int tid = threadIdx.x;

    for (int i = tid; i < 2400; i += 256) {
        int r = i >> 3, c4 = (i & 7) << 2;
        float4 kv = *(const float4*)(Kg + r*32 + c4);
        float4 vv = *(const float4*)(Vg + r*32 + c4);
        *(float4*)(Ks + r*36 + c4) = kv;
        *(float4*)(Vs + r*36 + c4) = vv;
    }
    for (int i = tid; i < 1200; i += 256) {
        int r = i >> 3, c4 = (i & 7) << 2;
        float4 qv = *(const float4*)(Qg + r*32 + c4);
        qv.x *= scale; qv.y *= scale; qv.z *= scale; qv.w *= scale;
        *(float4*)(Qs + r*32 + c4) = qv;
    }
    __syncthreads();

    const int warp = tid >> 5, lane = tid & 31;
    float* Pw = Ps + warp * 320;

    for (int q = warp; q < 150; q += 8) {
        float4 qr[8];
#pragma unroll
        for (int d4 = 0; d4 < 8; d4++) qr[d4] = *(const float4*)(Qs + q*32 + d4*4);

        float sc[10];
#pragma unroll
        for (int j = 0; j < 10; j++) {
            int k = j*32 + lane;
            float s = -1e30f;
            if (k < 300) {
                s = 0.f;
#pragma unroll
                for (int d4 = 0; d4 < 8; d4++) {
                    float4 kv = *(const float4*)(Ks + k*36 + d4*4);
                    s = fmaf(qr[d4].x, kv.x, s);
                    s = fmaf(qr[d4].y, kv.y, s);
                    s = fmaf(qr[d4].z, kv.z, s);
                    s = fmaf(qr[d4].w, kv.w, s);
                }
            }
            sc[j] = s;
        }
        float m = sc[0];
#pragma unroll
        for (int j = 1; j < 10; j++) m = fmaxf(m, sc[j]);
#pragma unroll
        for (int o = 16; o; o >>= 1) m = fmaxf(m, __shfl_xor_sync(0xffffffffu, m, o));
        float sum = 0.f;
#pragma unroll
        for (int j = 0; j < 10; j++) { sc[j] = expf(sc[j] - m); sum += sc[j]; }
#pragma unroll
        for (int o = 16; o; o >>= 1) sum += __shfl_xor_sync(0xffffffffu, sum, o);
        float inv = 1.f / sum;
#pragma unroll
        for (int j = 0; j < 10; j++) Pw[j*32 + lane] = sc[j] * inv;
        __syncwarp();

        float acc = 0.f;
#pragma unroll 4
        for (int k = 0; k < 300; k++)
            acc = fmaf(Pw[k], Vs[k*36 + lane], acc);

        int qg = half*150 + q;
        sa_in[((long)(qg*BSZ + b)) * DIM + h*DH + lane] = acc;
        __syncwarp();
    }
}

// ---------------- multi-scale deformable sampling ----------------
__global__ void __launch_bounds__(256) deform_kernel(
    const float* __restrict__ offaw,
    const float* __restrict__ bbox, const float* __restrict__ value,
    const int* __restrict__ spatial, const int* __restrict__ lstart,
    float* __restrict__ ca_in)
{
    __shared__ float s_w[8][32][4];
    __shared__ int   s_i[8][32][4];
    int bq = blockIdx.x;
    int b = bq / NQ, q = bq - b*NQ;
    int warp = threadIdx.x >> 5, lane = threadIdx.x & 31;

    const float* tok = offaw + (long)bq * 768;
    float a = tok[512 + warp*32 + lane];
    float m = a;
#pragma unroll
    for (int o = 16; o; o >>= 1) m = fmaxf(m, __shfl_xor_sync(0xffffffffu, m, o));
    float e = expf(a - m);
    float s = e;
#pragma unroll
    for (int o = 16; o; o >>= 1) s += __shfl_xor_sync(0xffffffffu, s, o);
    float p = e / s;

    float ox = tok[warp*64 + lane*2];
    float oy = tok[warp*64 + lane*2 + 1];
    const float* rb = bbox + ((long)q*BSZ + b)*4;
    float r0 = rb[0], r1 = rb[1], r2 = rb[2], r3 = rb[3];

    int lvl = lane >> 3;
    int H = spatial[lvl*2], W = spatial[lvl*2 + 1], ls = lstart[lvl];
    float Wf = (float)W, Hf = (float)H;
    float x = (r0 + ox*0.0625f*r2) * Wf - 0.5f;
    float y = (r1 + oy*0.0625f*r3) * Hf - 0.5f;
    float x0 = floorf(x), y0 = floorf(y);
    float fx = x - x0, fy = y - y0;

#pragma unroll
    for (int c = 0; c < 4; c++) {
        float xi = x0 + (float)(c & 1);
        float yi = y0 + (float)(c >> 1);
        float wgt = ((c & 1) ? fx : 1.f - fx) * ((c >> 1) ? fy : 1.f - fy);
        bool valid = (xi >= 0.f) && (xi < Wf) && (yi >= 0.f) && (yi < Hf);
        int xc = (int)fminf(fmaxf(xi, 0.f), Wf - 1.f);
        int yc = (int)fminf(fmaxf(yi, 0.f), Hf - 1.f);
        s_i[warp][lane][c] = ls + yc*W + xc;
        s_w[warp][lane][c] = valid ? wgt * p : 0.f;
    }
    __syncwarp();

    const float* vb = value + (long)b * STOT * DIM + warp*DH + lane;
    float acc = 0.f;
    for (int lp = 0; lp < 32; lp++) {
#pragma unroll
        for (int c = 0; c < 4; c++) {
            float wgt = s_w[warp][lp][c];
            if (wgt != 0.f)
                acc = fmaf(wgt, vb[(long)s_i[warp][lp][c] << 8], acc);
        }
    }
    ca_in[(long)bq*DIM + warp*DH + lane] = acc;
}

// ---------------- host orchestration ----------------
extern "C" void kernel_launch(void* const* d_in, const int* in_sizes, int n_in,
                              void* d_out, int out_size)
{
    const float* tgt        = (const float*)d_in[0];
    const float* qmask      = (const float*)d_in[1];
    const float* bbox       = (const float*)d_in[2];
    const float* memory     = (const float*)d_in[4];
    const float* in_proj_w  = (const float*)d_in[5];
    const float* in_proj_b  = (const float*)d_in[6];
    const float* out_sa_w   = (const float*)d_in[7];
    const float* out_sa_b   = (const float*)d_in[8];
    const float* norm2_g    = (const float*)d_in[9];
    const float* norm2_b    = (const float*)d_in[10];
    const float* value_w    = (const float*)d_in[11];
    const float* value_b    = (const float*)d_in[12];
    const float* off_w      = (const float*)d_in[13];
    const float* off_b      = (const float*)d_in[14];
    const float* aw_w       = (const float*)d_in[15];
    const float* aw_b       = (const float*)d_in[16];
    const float* out_ca_w   = (const float*)d_in[17];
    const float* out_ca_b   = (const float*)d_in[18];
    const float* norm1_g    = (const float*)d_in[19];
    const float* norm1_b    = (const float*)d_in[20];
    const float* lin1_w     = (const float*)d_in[21];
    const float* lin1_b     = (const float*)d_in[22];
    const float* lin2_w     = (const float*)d_in[23];
    const float* lin2_b     = (const float*)d_in[24];
    const float* norm3_g    = (const float*)d_in[25];
    const float* norm3_b    = (const float*)d_in[26];
    const unsigned char* pmask = (const unsigned char*)d_in[27];
    const int* spatial      = (const int*)d_in[28];
    const int* lstart       = (const int*)d_in[29];
    float* out = (float*)d_out;

    float *qbuf,*qh,*kh,*vh,*sain,*saout,*tgt2,*q2,*offb,*val,*cain,*caout,*tgt3,*f1,*f2;
    cudaGetSymbolAddress((void**)&qbuf,  g_qbuf);
    cudaGetSymbolAddress((void**)&qh,    g_qh);
    cudaGetSymbolAddress((void**)&kh,    g_kh);
    cudaGetSymbolAddress((void**)&vh,    g_vh);
    cudaGetSymbolAddress((void**)&sain,  g_sain);
    cudaGetSymbolAddress((void**)&saout, g_saout);
    cudaGetSymbolAddress((void**)&tgt2,  g_tgt2);
    cudaGetSymbolAddress((void**)&q2,    g_q2);
    cudaGetSymbolAddress((void**)&offb,  g_off);
    cudaGetSymbolAddress((void**)&val,   g_value);
    cudaGetSymbolAddress((void**)&cain,  g_cain);
    cudaGetSymbolAddress((void**)&caout, g_caout);
    cudaGetSymbolAddress((void**)&tgt3,  g_tgt3);
    cudaGetSymbolAddress((void**)&f1,    g_f1);
    cudaGetSymbolAddress((void**)&f2,    g_f2);

    // fork: value GEMM on side stream, overlapping the whole SA chain
    cudaStream_t sV;
    cudaStreamCreateWithFlags(&sV, cudaStreamNonBlocking);
    cudaEvent_t ev0, evJ;
    cudaEventCreateWithFlags(&ev0, cudaEventDisableTiming);
    cudaEventCreateWithFlags(&evJ, cudaEventDisableTiming);

    cudaEventRecord(ev0, 0);
    cudaStreamWaitEvent(sV, ev0, 0);

    // sV: value projection straight from fp32 memory (batched over BS), pad-mask epilogue
    launch_mma(3, memory, BSZ*DIM, 256, value_w, DIM, value_b,
               nullptr, nullptr, 0,
               val, nullptr, DIM, (long)STOT*DIM,
               STOT, DIM, DIM, BSZ, pmask, STOT, sV);
    cudaEventRecord(evJ, sV);

    // main: SA chain
    add_kernel<<<TOKF/4/256, 256>>>(tgt, qmask, qbuf, TOKF/4);

    launch_mma(2, qbuf, DIM, 0, in_proj_w, DIM, in_proj_b,
               nullptr, nullptr, 0, qh, kh, 0, 0, NTOK, 512, DIM, 1, nullptr, 0, 0);
    launch_mma(2, tgt, DIM, 0, in_proj_w + 512*256, DIM, in_proj_b + 512,
               nullptr, nullptr, 0, vh, nullptr, 0, 0, NTOK, 256, DIM, 1, nullptr, 0, 0);

    {
        int smem = (300*36*2 + 150*32 + 8*320) * 4;
        cudaFuncSetAttribute(attn_kernel, cudaFuncAttributeMaxDynamicSharedMemorySize, smem);
        attn_kernel<<<128, 256, smem>>>(qh, kh, vh, sain);
    }

    launch_mma(0, sain, DIM, 0, out_sa_w, DIM, out_sa_b,
               nullptr, nullptr, 0, saout, nullptr, DIM, 0, NTOK, DIM, DIM, 1, nullptr, 0, 0);
    ln_kernel<<<NTOK/8, 256>>>(tgt, saout, 0, norm2_g, norm2_b, tgt2);

    permadd_kernel<<<(TOKF/4 + 255)/256, 256>>>(tgt2, qmask, q2);

    launch_mma(0, q2, DIM, 0, off_w, DIM, off_b,
               aw_w, aw_b, 512,
               offb, nullptr, 768, 0, NTOK, 768, DIM, 1, nullptr, 0, 0);

    // join: deform needs val (sV) + offb (main)
    cudaStreamWaitEvent(0, evJ, 0);
    deform_kernel<<<NTOK, 256>>>(offb, bbox, val, spatial, lstart, cain);

    launch_mma(0, cain, DIM, 0, out_ca_w, DIM, out_ca_b,
               nullptr, nullptr, 0, caout, nullptr, DIM, 0, NTOK, DIM, DIM, 1, nullptr, 0, 0);
    ln_kernel<<<NTOK/8, 256>>>(tgt2, caout, 1, norm1_g, norm1_b, tgt3);

    launch_mma(1, tgt3, DIM, 0, lin1_w, DIM, lin1_b,
               nullptr, nullptr, 0, f1, nullptr, DFF, 0, NTOK, DFF, DIM, 1, nullptr, 0, 0);
    launch_mma(0, f1, DFF, 0, lin2_w, DFF, lin2_b,
               nullptr, nullptr, 0, f2, nullptr, DIM, 0, NTOK, DIM, DFF, 1, nullptr, 0, 0);
    ln_kernel<<<NTOK/8, 256>>>(tgt3, f2, 0, norm3_g, norm3_b, out);
}